// round 14
// baseline (speedup 1.0000x reference)
#include <cuda_runtime.h>
#include <math.h>

// Shapes: B=2, I=20, J=32, D=256, S=640, gates=768
__device__ float4 g_w1p4[49152];
__device__ float4 g_j1p4[16384];
__device__ float4 g_j2p4[16384];
__device__ float g_tokxg[29*768];
__device__ float g_hbuf[2][128][256];
__device__ float g_y0[2560*256];
__device__ float g_xg1[2560*768];
__device__ float g_e[4*640*256];
__device__ float g_q[1280*256];
__device__ float g_k[1280*256];
__device__ float g_sum[2];
__device__ float g_pp[512];
__device__ float g_pool[2*2048];
__device__ float g_y1[2*600];
__device__ volatile unsigned g_f0[5][2][16];   // [rowg][lane][dsl]
__device__ volatile unsigned g_f1[8][2][16];

__device__ __forceinline__ float sigm(float x){ return 1.0f/(1.0f+expf(-x)); }

__device__ __forceinline__ unsigned long long pk2(float a, float b){
  unsigned long long r;
  asm("mov.b64 %0, {%1, %2};" : "=l"(r) : "f"(a), "f"(b));
  return r;
}
__device__ __forceinline__ float s2(unsigned long long v){
  float a, b;
  asm("mov.b64 {%0, %1}, %2;" : "=f"(a), "=f"(b) : "l"(v));
  return a + b;
}
__device__ __forceinline__ unsigned long long mul2(unsigned long long a, unsigned long long b){
  unsigned long long r;
  asm("mul.rn.f32x2 %0, %1, %2;" : "=l"(r) : "l"(a), "l"(b));
  return r;
}
__device__ __forceinline__ void fma2(unsigned long long &d, unsigned long long a, unsigned long long b){
  asm("fma.rn.f32x2 %0, %1, %2, %0;" : "+l"(d) : "l"(a), "l"(b));
}
__device__ __forceinline__ unsigned long long fma2r(unsigned long long a, unsigned long long b, unsigned long long c){
  unsigned long long r;
  asm("fma.rn.f32x2 %0, %1, %2, %3;" : "=l"(r) : "l"(a), "l"(b), "l"(c));
  return r;
}

__global__ void k_nop(){}

// ---------------- pack weights + zero accumulators/flags --------------------
__global__ void k_pack(const float* __restrict__ wih1, const float* __restrict__ ja1,
                       const float* __restrict__ ja2){
  int idx = blockIdx.x*256 + threadIdx.x;
  if (idx < 49152){
    int g = idx % 768, k4 = idx / 768;
    g_w1p4[idx] = *(const float4*)(wih1 + g*256 + k4*4);
  } else if (idx < 65536){
    int i = idx - 49152; int d = i % 256, k4 = i / 256;
    g_j1p4[i] = *(const float4*)(ja1 + d*256 + k4*4);
  } else {
    int i = idx - 65536; int d = i % 256, k4 = i / 256;
    g_j2p4[i] = *(const float4*)(ja2 + d*256 + k4*4);
  }
  if (idx < 512) g_pp[idx] = 0.f;
  if (idx < 2)   g_sum[idx] = 0.f;
  if (idx < 160) ((volatile unsigned*)g_f0)[idx] = 0u;
  if (idx < 256) ((volatile unsigned*)g_f1)[idx] = 0u;
}

// ---------------- token -> GRU0 input-gate table (29 x 768) -----------------
__global__ void k_tokxg(const float* __restrict__ emb, const float* __restrict__ wih0,
                        const float* __restrict__ bih0){
  __shared__ __align__(16) float se[256];
  int tok = blockIdx.x, g = threadIdx.x;
  if (g < 256) se[g] = emb[tok*256+g];
  __syncthreads();
  const ulonglong2* w2 = (const ulonglong2*)(wih0 + g*256);
  const ulonglong2* e2 = (const ulonglong2*)se;
  unsigned long long acc = 0ull;
  #pragma unroll 8
  for (int k=0;k<64;k++){
    ulonglong2 w = w2[k]; ulonglong2 e = e2[k];
    fma2(acc, w.x, e.x); fma2(acc, w.y, e.y);
  }
  g_tokxg[tok*768+g] = bih0[g] + s2(acc);
}

// ---------------- GRU0 persistent scan, 2-lane staggered --------------------
// grid (16,5) x 128. thread: ks=tid>>4, dl=tid&15.
__global__ void __launch_bounds__(128,1) k_gru0_scan(
    const float* __restrict__ whh, const float* __restrict__ bhh,
    const int* __restrict__ p1, const int* __restrict__ p2){
  __shared__ __align__(16) float shh[16*260];
  __shared__ float red[4*8*3*16];   // [w][row-in-lane][gate][dl]
  __shared__ int stok[16*32];
  int tid = threadIdx.x;
  int dsl = blockIdx.x, rowg = blockIdx.y;
  int ks = tid >> 4, dl = tid & 15;
  int lane = tid & 31, w = tid >> 5;
  int dg = dsl*16 + dl;

  ulonglong2 warr[3][8];
  #pragma unroll
  for (int g=0; g<3; g++){
    const float* base = whh + (g*256 + dg)*256 + ks*32;
    #pragma unroll
    for (int jj=0; jj<8; jj++) warr[g][jj] = *(const ulonglong2*)(base + jj*4);
  }
  for (int i = tid; i < 16*32; i += 128){
    int rr = i>>5, t = i&31;
    int gr = rowg*16 + rr;
    int p = gr/40, rem = gr - p*40, b = rem/20, ii = rem - b*20;
    stok[rr*32+t] = (p ? p2 : p1)[b*640 + ii*32 + t];
  }
  float br = bhh[dg], bz = bhh[256+dg], bn = bhh[512+dg];
  __syncthreads();

  for (int t=0; t<32; t++){
    #pragma unroll
    for (int L=0; L<2; L++){
      int rbase = L*8;
      if (t > 0){
        if (tid < 16) while (g_f0[rowg][L][tid] < (unsigned)t) { }
        __threadfence();
      }
      __syncthreads();
      if (t == 0){
        for (int i=tid; i<8*64; i+=128)
          ((float4*)(shh+(rbase+(i>>6))*260))[i&63] = make_float4(0.f,0.f,0.f,0.f);
      } else {
        int par = t & 1;
        for (int i=tid; i<8*64; i+=128)
          ((float4*)(shh+(rbase+(i>>6))*260))[i&63] =
              __ldcg(((const float4*)&g_hbuf[par][rowg*16+rbase+(i>>6)][0]) + (i&63));
      }
      __syncthreads();

      int myrow = rbase + ks;
      const float* xg = g_tokxg + stok[myrow*32+t]*768;
      float xr=xg[dg], xz=xg[256+dg], xn=xg[512+dg];
      float hp = shh[myrow*260+dg];

      #pragma unroll
      for (int rc=0; rc<2; rc++){
        unsigned long long acc[4][3] = {};
        const float* hb = shh + (rbase + rc*4)*260 + ks*32;
        #pragma unroll
        for (int jj=0; jj<8; jj++){
          #pragma unroll
          for (int q=0; q<4; q++){
            ulonglong2 h2 = *(const ulonglong2*)(hb + q*260 + jj*4);
            fma2(acc[q][0], warr[0][jj].x, h2.x); fma2(acc[q][0], warr[0][jj].y, h2.y);
            fma2(acc[q][1], warr[1][jj].x, h2.x); fma2(acc[q][1], warr[1][jj].y, h2.y);
            fma2(acc[q][2], warr[2][jj].x, h2.x); fma2(acc[q][2], warr[2][jj].y, h2.y);
          }
        }
        #pragma unroll
        for (int q=0; q<4; q++){
          #pragma unroll
          for (int g=0; g<3; g++){
            float s = s2(acc[q][g]);
            s += __shfl_xor_sync(0xffffffffu, s, 16);
            if (lane < 16) red[((w*8 + rc*4+q)*3 + g)*16 + dl] = s;
          }
        }
      }
      __syncthreads();

      {
        int rl = ks, gr = rowg*16 + myrow;
        float ar = br + red[((0+rl)*3+0)*16+dl] + red[((8+rl)*3+0)*16+dl]
                      + red[((16+rl)*3+0)*16+dl] + red[((24+rl)*3+0)*16+dl];
        float az = bz + red[((0+rl)*3+1)*16+dl] + red[((8+rl)*3+1)*16+dl]
                      + red[((16+rl)*3+1)*16+dl] + red[((24+rl)*3+1)*16+dl];
        float an = bn + red[((0+rl)*3+2)*16+dl] + red[((8+rl)*3+2)*16+dl]
                      + red[((16+rl)*3+2)*16+dl] + red[((24+rl)*3+2)*16+dl];
        float rr_ = sigm(xr + ar);
        float zz  = sigm(xz + az);
        float nn  = tanhf(xn + rr_*an);
        float hv  = (1.f-zz)*nn + zz*hp;
        g_hbuf[(t+1)&1][gr][dg] = hv;
        g_y0[(gr*32+t)*256+dg] = hv;
      }
      __threadfence();
      __syncthreads();
      if (tid == 0) g_f0[rowg][L][dsl] = (unsigned)(t+1);
    }
  }
}

// ---------------- GRU1 input gates: 2 cols/thread, prefetched weights -------
__global__ void __launch_bounds__(384) k_xg1(const float* __restrict__ bih1){
  __shared__ __align__(16) float sa[20][260];
  int tid = threadIdx.x;
  int m0 = blockIdx.x*20;
  for (int i=tid; i<20*64; i+=384){
    int r=i/64, k4=i%64;
    ((float4*)&sa[r][0])[k4] = *((const float4*)(g_y0 + (m0+r)*256) + k4);
  }
  __syncthreads();
  unsigned long long acc0[20], acc1[20];
  #pragma unroll
  for (int r=0;r<20;r++){ acc0[r]=0ull; acc1[r]=0ull; }
  const ulonglong2* wp = (const ulonglong2*)g_w1p4;
  int c0 = tid, c1 = tid + 384;
  ulonglong2 w0 = wp[c0], w1 = wp[c1];
  for (int k4=0;k4<64;k4++){
    ulonglong2 nw0, nw1;
    if (k4 < 63){
      nw0 = wp[(k4+1)*768 + c0];
      nw1 = wp[(k4+1)*768 + c1];
    }
    #pragma unroll
    for (int r=0;r<20;r++){
      ulonglong2 h = ((const ulonglong2*)&sa[r][0])[k4];
      fma2(acc0[r], w0.x, h.x); fma2(acc0[r], w0.y, h.y);
      fma2(acc1[r], w1.x, h.x); fma2(acc1[r], w1.y, h.y);
    }
    w0 = nw0; w1 = nw1;
  }
  float b0 = bih1[c0], b1 = bih1[c1];
  #pragma unroll
  for (int r=0;r<20;r++){
    g_xg1[(m0+r)*768 + c0] = b0 + s2(acc0[r]);
    g_xg1[(m0+r)*768 + c1] = b1 + s2(acc1[r]);
  }
}

// ---------------- GRU1 persistent scan, 2-lane staggered --------------------
// grid (16,8) x 128
__global__ void __launch_bounds__(128,1) k_gru1_scan(
    const float* __restrict__ whh, const float* __restrict__ bhh){
  __shared__ __align__(16) float shh[16*260];
  __shared__ float red[4*8*3*16];
  int tid = threadIdx.x;
  int dsl = blockIdx.x, rowg = blockIdx.y;
  int ks = tid >> 4, dl = tid & 15;
  int lane = tid & 31, w = tid >> 5;
  int dg = dsl*16 + dl;

  ulonglong2 warr[3][8];
  #pragma unroll
  for (int g=0; g<3; g++){
    const float* base = whh + (g*256 + dg)*256 + ks*32;
    #pragma unroll
    for (int jj=0; jj<8; jj++) warr[g][jj] = *(const ulonglong2*)(base + jj*4);
  }
  float br = bhh[dg], bz = bhh[256+dg], bn = bhh[512+dg];
  __syncthreads();

  for (int t=0; t<20; t++){
    #pragma unroll
    for (int L=0; L<2; L++){
      int rbase = L*8;
      if (t > 0){
        if (tid < 16) while (g_f1[rowg][L][tid] < (unsigned)t) { }
        __threadfence();
      }
      __syncthreads();
      if (t == 0){
        for (int i=tid; i<8*64; i+=128)
          ((float4*)(shh+(rbase+(i>>6))*260))[i&63] = make_float4(0.f,0.f,0.f,0.f);
      } else {
        int par = t & 1;
        for (int i=tid; i<8*64; i+=128)
          ((float4*)(shh+(rbase+(i>>6))*260))[i&63] =
              __ldcg(((const float4*)&g_hbuf[par][rowg*16+rbase+(i>>6)][0]) + (i&63));
      }
      __syncthreads();

      int myrow = rbase + ks;
      int gr = rowg*16 + myrow;
      int p = gr>>6, b = (gr>>5)&1, R = gr&31;
      int xrow = (p*2+b)*640 + R*20 + t;
      const float* xg = g_xg1 + xrow*768;
      float xr=xg[dg], xz=xg[256+dg], xn=xg[512+dg];
      float hp = shh[myrow*260+dg];

      #pragma unroll
      for (int rc=0; rc<2; rc++){
        unsigned long long acc[4][3] = {};
        const float* hb = shh + (rbase + rc*4)*260 + ks*32;
        #pragma unroll
        for (int jj=0; jj<8; jj++){
          #pragma unroll
          for (int q=0; q<4; q++){
            ulonglong2 h2 = *(const ulonglong2*)(hb + q*260 + jj*4);
            fma2(acc[q][0], warr[0][jj].x, h2.x); fma2(acc[q][0], warr[0][jj].y, h2.y);
            fma2(acc[q][1], warr[1][jj].x, h2.x); fma2(acc[q][1], warr[1][jj].y, h2.y);
            fma2(acc[q][2], warr[2][jj].x, h2.x); fma2(acc[q][2], warr[2][jj].y, h2.y);
          }
        }
        #pragma unroll
        for (int q=0; q<4; q++){
          #pragma unroll
          for (int g=0; g<3; g++){
            float s = s2(acc[q][g]);
            s += __shfl_xor_sync(0xffffffffu, s, 16);
            if (lane < 16) red[((w*8 + rc*4+q)*3 + g)*16 + dl] = s;
          }
        }
      }
      __syncthreads();

      {
        int rl = ks;
        float ar = br + red[((0+rl)*3+0)*16+dl] + red[((8+rl)*3+0)*16+dl]
                      + red[((16+rl)*3+0)*16+dl] + red[((24+rl)*3+0)*16+dl];
        float az = bz + red[((0+rl)*3+1)*16+dl] + red[((8+rl)*3+1)*16+dl]
                      + red[((16+rl)*3+1)*16+dl] + red[((24+rl)*3+1)*16+dl];
        float an = bn + red[((0+rl)*3+2)*16+dl] + red[((8+rl)*3+2)*16+dl]
                      + red[((16+rl)*3+2)*16+dl] + red[((24+rl)*3+2)*16+dl];
        float rr_ = sigm(xr + ar);
        float zz  = sigm(xz + az);
        float nn  = tanhf(xn + rr_*an);
        float hv  = (1.f-zz)*nn + zz*hp;
        g_hbuf[(t+1)&1][gr][dg] = hv;
        g_e[xrow*256+dg] = hv;
      }
      __threadfence();
      __syncthreads();
      if (tid == 0) g_f1[rowg][L][dsl] = (unsigned)(t+1);
    }
  }
}

// ---------------- q/k projection: prefetched packed GEMM --------------------
__global__ void __launch_bounds__(256) k_qk(
    const float* __restrict__ b1, const float* __restrict__ b2){
  __shared__ __align__(16) float sa[32][260];
  int tid = threadIdx.x;
  int which = blockIdx.y;
  int m0 = blockIdx.x*32;
  for (int i=tid; i<32*64; i+=256){
    int r=i>>6, k4=i&63;
    float4 v = *((const float4*)(g_e + (which*1280 + m0 + r)*256) + k4);
    v.x = v.x>0.f?v.x:0.f; v.y = v.y>0.f?v.y:0.f;
    v.z = v.z>0.f?v.z:0.f; v.w = v.w>0.f?v.w:0.f;
    ((float4*)&sa[r][0])[k4] = v;
  }
  __syncthreads();
  const ulonglong2* wp = (const ulonglong2*)(which ? g_j2p4 : g_j1p4);
  unsigned long long acc[32];
  #pragma unroll
  for (int r=0;r<32;r++) acc[r]=0ull;
  ulonglong2 w = wp[tid];
  for (int k4=0;k4<64;k4++){
    ulonglong2 nw;
    if (k4 < 63) nw = wp[(k4+1)*256 + tid];
    #pragma unroll
    for (int r=0;r<32;r++){
      ulonglong2 h = ((const ulonglong2*)&sa[r][0])[k4];
      fma2(acc[r], w.x, h.x);
      fma2(acc[r], w.y, h.y);
    }
    w = nw;
  }
  float bb = (which ? b2 : b1)[tid];
  float* out = which ? g_k : g_q;
  #pragma unroll
  for (int r=0;r<32;r++) out[(m0+r)*256+tid] = bb + s2(acc[r]);
}

// ---------------- inter (unnormalized sigmoid) + per-batch sum --------------
__global__ void k_inter(float* __restrict__ outp){
  __shared__ __align__(16) float qs[32][66], ks[32][66];
  __shared__ float red[256];
  int tid = threadIdx.x;
  int b = blockIdx.z, s0 = blockIdx.x*32, t0 = blockIdx.y*32;
  int si = tid>>3, tj = (tid&7)*4;
  unsigned long long a2[4] = {0ull,0ull,0ull,0ull};
  for (int kc=0; kc<4; kc++){
    for (int i=tid; i<2048; i+=256){
      int r = i>>6, c = i&63;
      qs[r][c] = g_q[(b*640+s0+r)*256 + kc*64 + c];
      ks[r][c] = g_k[(b*640+t0+r)*256 + kc*64 + c];
    }
    __syncthreads();
    #pragma unroll 8
    for (int kp=0;kp<32;kp++){
      unsigned long long qv = *(const unsigned long long*)&qs[si][2*kp];
      fma2(a2[0], qv, *(const unsigned long long*)&ks[tj+0][2*kp]);
      fma2(a2[1], qv, *(const unsigned long long*)&ks[tj+1][2*kp]);
      fma2(a2[2], qv, *(const unsigned long long*)&ks[tj+2][2*kp]);
      fma2(a2[3], qv, *(const unsigned long long*)&ks[tj+3][2*kp]);
    }
    __syncthreads();
  }
  float lsum = 0.f;
  #pragma unroll
  for (int u=0;u<4;u++){
    float v = sigm(s2(a2[u]));
    outp[b*409600 + (s0+si)*640 + (t0+tj+u)] = v;
    lsum += v;
  }
  red[tid]=lsum; __syncthreads();
  for (int off=128; off>0; off>>=1){ if (tid<off) red[tid]+=red[tid+off]; __syncthreads(); }
  if (tid==0) atomicAdd(&g_sum[b], red[0]);
}

// ---------------- pp accumulate (f32x2 poly) + normalize inter in place -----
__global__ void k_pp(float* __restrict__ outp){
  __shared__ __align__(16) float w[32][34];
  int tid = threadIdx.x, d = tid;
  int b = blockIdx.z, s0 = blockIdx.x*32, t0 = blockIdx.y*32;
  for (int i=tid; i<1024; i+=256){
    int si = i>>5, ti = i&31;
    w[si][ti] = outp[b*409600 + (s0+si)*640 + t0+ti];
  }
  float e2v[32]; float m2 = 0.f;
  #pragma unroll
  for (int ti=0; ti<32; ti++){
    e2v[ti] = g_e[((2+b)*640 + t0+ti)*256 + d];
    m2 = fmaxf(m2, fabsf(e2v[ti]));
  }
  unsigned long long e2p[16];
  #pragma unroll
  for (int u=0;u<16;u++) e2p[u] = pk2(e2v[2*u], e2v[2*u+1]);
  __syncthreads();
  const unsigned long long C5 = pk2(-0.0088632355f,-0.0088632355f);
  const unsigned long long C4 = pk2( 0.021869488f,  0.021869488f);
  const unsigned long long C3 = pk2(-0.053968254f, -0.053968254f);
  const unsigned long long C2 = pk2( 0.13333334f,   0.13333334f);
  const unsigned long long C1 = pk2(-0.33333334f,  -0.33333334f);
  unsigned long long acc2 = 0ull;
  float accS = 0.f;
  #pragma unroll 1
  for (int si=0; si<32; si++){
    float a = g_e[(b*640 + s0+si)*256 + d];
    if (fabsf(a)*m2 <= 0.6f){
      unsigned long long a2 = pk2(a, a);
      #pragma unroll
      for (int u=0;u<16;u++){
        unsigned long long x2 = mul2(a2, e2p[u]);
        unsigned long long u2 = mul2(x2, x2);
        unsigned long long p  = fma2r(u2, C5, C4);
        p = fma2r(u2, p, C3);
        p = fma2r(u2, p, C2);
        p = fma2r(u2, p, C1);
        unsigned long long tv = fma2r(mul2(x2,u2), p, x2);
        fma2(acc2, *(const unsigned long long*)&w[si][2*u], tv);
      }
    } else {
      for (int ti=0; ti<32; ti++){
        float x = a * g_e[((2+b)*640 + t0+ti)*256 + d];
        accS = fmaf(w[si][ti], tanhf(x), accS);
      }
    }
  }
  atomicAdd(&g_pp[b*256+d], accS + s2(acc2));
  float inv = 1.f/g_sum[b];
  for (int i=tid; i<1024; i+=256){
    int si = i>>5, ti = i&31;
    outp[b*409600 + (s0+si)*640 + t0+ti] = w[si][ti]*inv;
  }
}

// ---------------- head A: conv + leaky + maxpool; seed y1 with bias ---------
__global__ void k_headA(const float* __restrict__ cw_, const float* __restrict__ cb_,
                        const float* __restrict__ r1b){
  __shared__ float pp[256];
  __shared__ float cw[256];
  __shared__ float cb[64];
  int b = blockIdx.x, tid = threadIdx.x;
  float inv = 1.f/g_sum[b];
  pp[tid] = g_pp[b*256+tid]*inv;
  cw[tid] = cw_[tid];
  if (tid<64) cb[tid]=cb_[tid];
  __syncthreads();
  for (int idx=tid; idx<2048; idx+=256){
    int o = idx>>5, m = idx&31;
    float mx = -1e30f;
    for (int q=0;q<4;q++){
      int l = m*4+q;
      float s = cb[o];
      #pragma unroll
      for (int kk=0;kk<4;kk++){
        int pos = 2*l - 1 + kk;
        if (pos>=0 && pos<256) s = fmaf(pp[pos], cw[o*4+kk], s);
      }
      s = s>0.f ? s : 0.1f*s;
      mx = fmaxf(mx, s);
    }
    g_pool[b*2048+idx] = mx;
  }
  for (int j=tid; j<600; j+=256) g_y1[b*600+j] = r1b[j];
}

// ---------------- head B: r1 GEMV warp-per-row, k-split grid (4,2) ----------
__global__ void __launch_bounds__(256) k_headB(const float* __restrict__ r1w){
  __shared__ __align__(16) float spool[512];
  int kb = blockIdx.x, b = blockIdx.y;
  int tid = threadIdx.x, wid = tid>>5, lane = tid&31;
  for (int i=tid; i<512; i+=256) spool[i] = g_pool[b*2048 + kb*512 + i];
  __syncthreads();
  for (int j = wid; j < 600; j += 8){
    const float4* wr = (const float4*)(r1w + j*2048 + kb*512);
    float s = 0.f;
    #pragma unroll
    for (int it=0; it<4; it++){
      float4 wv = wr[it*32 + lane];
      float4 pv = *(const float4*)&spool[(it*32+lane)*4];
      s += wv.x*pv.x + wv.y*pv.y + wv.z*pv.z + wv.w*pv.w;
    }
    #pragma unroll
    for (int off=16; off; off>>=1) s += __shfl_xor_sync(0xffffffffu, s, off);
    if (lane==0) atomicAdd(&g_y1[b*600+j], s);
  }
}

// ---------------- head C: leaky -> r2 -> leaky -> r3 -> affn ----------------
__global__ void k_headC(const float* __restrict__ r2w, const float* __restrict__ r2b,
                        const float* __restrict__ r3w, const float* __restrict__ r3b,
                        float* __restrict__ outp){
  __shared__ __align__(16) float y1s[600];
  __shared__ float y2s[300];
  __shared__ float red[256];
  int b = blockIdx.x, tid = threadIdx.x;
  int wid = tid>>5, lane = tid&31;
  for (int j=tid; j<600; j+=256){
    float v = g_y1[b*600+j];
    y1s[j] = v>0.f ? v : 0.1f*v;
  }
  __syncthreads();
  for (int j = wid; j < 300; j += 8){
    const float* wr = r2w + j*600;
    float s = 0.f;
    for (int k = lane*4; k < 600; k += 128){
      float4 wv = *(const float4*)(wr + k);
      s += wv.x*y1s[k] + wv.y*y1s[k+1] + wv.z*y1s[k+2] + wv.w*y1s[k+3];
    }
    #pragma unroll
    for (int off=16; off; off>>=1) s += __shfl_xor_sync(0xffffffffu, s, off);
    if (lane==0){
      float v = s + r2b[j];
      y2s[j] = v>0.f ? v : 0.1f*v;
    }
  }
  __syncthreads();
  float part = 0.f;
  for (int k=tid; k<300; k+=256) part = fmaf(y2s[k], r3w[k], part);
  red[tid]=part; __syncthreads();
  for (int off=128; off>0; off>>=1){ if (tid<off) red[tid]+=red[tid+off]; __syncthreads(); }
  if (tid==0) outp[819200+b] = red[0] + r3b[0];
}

// ---------------- launch ----------------------------------------------------
extern "C" void kernel_launch(void* const* d_in, const int* in_sizes, int n_in,
                              void* d_out, int out_size){
  const int*   p1     = (const int*)  d_in[0];
  const int*   p2     = (const int*)  d_in[1];
  const float* emb    = (const float*)d_in[2];
  const float* g0_wih = (const float*)d_in[3];
  const float* g0_whh = (const float*)d_in[4];
  const float* g0_bih = (const float*)d_in[5];
  const float* g0_bhh = (const float*)d_in[6];
  const float* g1_wih = (const float*)d_in[7];
  const float* g1_whh = (const float*)d_in[8];
  const float* g1_bih = (const float*)d_in[9];
  const float* g1_bhh = (const float*)d_in[10];
  const float* ja1_w  = (const float*)d_in[11];
  const float* ja1_b  = (const float*)d_in[12];
  const float* ja2_w  = (const float*)d_in[13];
  const float* ja2_b  = (const float*)d_in[14];
  const float* conv_w = (const float*)d_in[15];
  const float* conv_b = (const float*)d_in[16];
  const float* r1w    = (const float*)d_in[17];
  const float* r1b    = (const float*)d_in[18];
  const float* r2w    = (const float*)d_in[19];
  const float* r2b    = (const float*)d_in[20];
  const float* r3w    = (const float*)d_in[21];
  const float* r3b    = (const float*)d_in[22];
  float* outp = (float*)d_out;

  k_nop<<<1,32>>>();
  k_pack<<<320,256>>>(g1_wih, ja1_w, ja2_w);
  k_tokxg<<<29,768>>>(emb, g0_wih, g0_bih);
  k_gru0_scan<<<dim3(16,5),128>>>(g0_whh, g0_bhh, p1, p2);
  k_xg1<<<128,384>>>(g1_bih);
  k_gru1_scan<<<dim3(16,8),128>>>(g1_whh, g1_bhh);
  k_qk<<<dim3(40,2),256>>>(ja1_b, ja2_b);
  dim3 gi(20,20,2);
  k_inter<<<gi,256>>>(outp);
  k_pp<<<gi,256>>>(outp);
  k_headA<<<2,256>>>(conv_w, conv_b, r1b);
  k_headB<<<dim3(4,2),256>>>(r1w);
  k_headC<<<2,256>>>(r2w, r2b, r3w, r3b, outp);
}

// round 15
// speedup vs baseline: 1.1956x; 1.1956x over previous
#include <cuda_runtime.h>
#include <math.h>

// Shapes: B=2, I=20, J=32, D=256, S=640, gates=768
__device__ float4 g_w1p4[49152];
__device__ float4 g_j1p4[16384];
__device__ float4 g_j2p4[16384];
__device__ float g_tokxg[29*768];
__device__ float g_hbuf[2][128][256];
__device__ float g_y0[2560*256];
__device__ float g_xg1[2560*768];
__device__ float g_e[4*640*256];
__device__ float g_q[1280*256];
__device__ float g_k[1280*256];
__device__ float g_sum[2];
__device__ float g_pp[512];
__device__ float g_pool[2*2048];
__device__ float g_y1[2*600];
__device__ volatile unsigned g_bf0[5][16];   // [rowg][dsl] step counters
__device__ volatile unsigned g_bf1[8][16];

__device__ __forceinline__ float sigm(float x){ return 1.0f/(1.0f+expf(-x)); }

__device__ __forceinline__ unsigned long long pk2(float a, float b){
  unsigned long long r;
  asm("mov.b64 %0, {%1, %2};" : "=l"(r) : "f"(a), "f"(b));
  return r;
}
__device__ __forceinline__ float s2(unsigned long long v){
  float a, b;
  asm("mov.b64 {%0, %1}, %2;" : "=f"(a), "=f"(b) : "l"(v));
  return a + b;
}
__device__ __forceinline__ unsigned long long mul2(unsigned long long a, unsigned long long b){
  unsigned long long r;
  asm("mul.rn.f32x2 %0, %1, %2;" : "=l"(r) : "l"(a), "l"(b));
  return r;
}
__device__ __forceinline__ void fma2(unsigned long long &d, unsigned long long a, unsigned long long b){
  asm("fma.rn.f32x2 %0, %1, %2, %0;" : "+l"(d) : "l"(a), "l"(b));
}
__device__ __forceinline__ unsigned long long fma2r(unsigned long long a, unsigned long long b, unsigned long long c){
  unsigned long long r;
  asm("fma.rn.f32x2 %0, %1, %2, %3;" : "=l"(r) : "l"(a), "l"(b), "l"(c));
  return r;
}

__global__ void k_nop(){}

// ---------------- pack weights + zero accumulators/flags --------------------
__global__ void k_pack(const float* __restrict__ wih1, const float* __restrict__ ja1,
                       const float* __restrict__ ja2){
  int idx = blockIdx.x*256 + threadIdx.x;
  if (idx < 49152){
    int g = idx % 768, k4 = idx / 768;
    g_w1p4[idx] = *(const float4*)(wih1 + g*256 + k4*4);
  } else if (idx < 65536){
    int i = idx - 49152; int d = i % 256, k4 = i / 256;
    g_j1p4[i] = *(const float4*)(ja1 + d*256 + k4*4);
  } else {
    int i = idx - 65536; int d = i % 256, k4 = i / 256;
    g_j2p4[i] = *(const float4*)(ja2 + d*256 + k4*4);
  }
  if (idx < 512) g_pp[idx] = 0.f;
  if (idx < 2)   g_sum[idx] = 0.f;
  if (idx < 80)  ((volatile unsigned*)g_bf0)[idx] = 0u;
  if (idx < 128) ((volatile unsigned*)g_bf1)[idx] = 0u;
}

// ---------------- token -> GRU0 input-gate table (29 x 768) -----------------
__global__ void k_tokxg(const float* __restrict__ emb, const float* __restrict__ wih0,
                        const float* __restrict__ bih0){
  __shared__ __align__(16) float se[256];
  int tok = blockIdx.x, g = threadIdx.x;
  if (g < 256) se[g] = emb[tok*256+g];
  __syncthreads();
  const ulonglong2* w2 = (const ulonglong2*)(wih0 + g*256);
  const ulonglong2* e2 = (const ulonglong2*)se;
  unsigned long long acc = 0ull;
  #pragma unroll 8
  for (int k=0;k<64;k++){
    ulonglong2 w = w2[k]; ulonglong2 e = e2[k];
    fma2(acc, w.x, e.x); fma2(acc, w.y, e.y);
  }
  g_tokxg[tok*768+g] = bih0[g] + s2(acc);
}

// ---------------- GRU0 persistent scan, reg-weights, flag barrier -----------
// grid (16,5) x 128. thread: ks=tid>>4, dl=tid&15.
__global__ void __launch_bounds__(128,1) k_gru0_scan(
    const float* __restrict__ whh, const float* __restrict__ bhh,
    const int* __restrict__ p1, const int* __restrict__ p2){
  __shared__ __align__(16) float shh[16*260];
  __shared__ float red[4*16*3*16];   // [w][row][gate][dl]
  __shared__ int stok[16*32];
  int tid = threadIdx.x;
  int dsl = blockIdx.x, rowg = blockIdx.y;
  int ks = tid >> 4, dl = tid & 15;
  int lane = tid & 31, w = tid >> 5;
  int dg = dsl*16 + dl;

  ulonglong2 warr[3][8];
  #pragma unroll
  for (int g=0; g<3; g++){
    const float* base = whh + (g*256 + dg)*256 + ks*32;
    #pragma unroll
    for (int jj=0; jj<8; jj++) warr[g][jj] = *(const ulonglong2*)(base + jj*4);
  }
  for (int i = tid; i < 16*32; i += 128){
    int rr = i>>5, t = i&31;
    int gr = rowg*16 + rr;
    int p = gr/40, rem = gr - p*40, b = rem/20, ii = rem - b*20;
    stok[rr*32+t] = (p ? p2 : p1)[b*640 + ii*32 + t];
  }
  float br = bhh[dg], bz = bhh[256+dg], bn = bhh[512+dg];
  int r2 = ks;
  __syncthreads();

  for (int t=0; t<32; t++){
    if (t > 0){
      if (tid < 16) while (g_bf0[rowg][tid] < (unsigned)t) { }
      __threadfence();
    }
    __syncthreads();
    if (t == 0){
      for (int i=tid; i<16*64; i+=128)
        ((float4*)(shh+(i>>6)*260))[i&63] = make_float4(0.f,0.f,0.f,0.f);
    } else {
      int par = t & 1;
      for (int i=tid; i<16*64; i+=128)
        ((float4*)(shh+(i>>6)*260))[i&63] =
            __ldcg(((const float4*)&g_hbuf[par][rowg*16+(i>>6)][0]) + (i&63));
    }
    __syncthreads();

    const float* xga = g_tokxg + stok[r2*32+t]*768;
    const float* xgb = g_tokxg + stok[(r2+8)*32+t]*768;
    float xar=xga[dg], xaz=xga[256+dg], xan=xga[512+dg];
    float xbr=xgb[dg], xbz=xgb[256+dg], xbn=xgb[512+dg];

    #pragma unroll
    for (int rc=0; rc<4; rc++){
      unsigned long long acc[4][3] = {};
      const float* hb = shh + (rc*4)*260 + ks*32;
      #pragma unroll
      for (int jj=0; jj<8; jj++){
        #pragma unroll
        for (int q=0; q<4; q++){
          ulonglong2 h2 = *(const ulonglong2*)(hb + q*260 + jj*4);
          fma2(acc[q][0], warr[0][jj].x, h2.x); fma2(acc[q][0], warr[0][jj].y, h2.y);
          fma2(acc[q][1], warr[1][jj].x, h2.x); fma2(acc[q][1], warr[1][jj].y, h2.y);
          fma2(acc[q][2], warr[2][jj].x, h2.x); fma2(acc[q][2], warr[2][jj].y, h2.y);
        }
      }
      #pragma unroll
      for (int q=0; q<4; q++){
        #pragma unroll
        for (int g=0; g<3; g++){
          float s = s2(acc[q][g]);
          s += __shfl_xor_sync(0xffffffffu, s, 16);
          if (lane < 16) red[((w*16 + rc*4+q)*3 + g)*16 + dl] = s;
        }
      }
    }
    __syncthreads();

    {
      int row = r2, gr = rowg*16 + row;
      float ar = br + red[((0+row)*3+0)*16+dl] + red[((16+row)*3+0)*16+dl]
                    + red[((32+row)*3+0)*16+dl] + red[((48+row)*3+0)*16+dl];
      float az = bz + red[((0+row)*3+1)*16+dl] + red[((16+row)*3+1)*16+dl]
                    + red[((32+row)*3+1)*16+dl] + red[((48+row)*3+1)*16+dl];
      float an = bn + red[((0+row)*3+2)*16+dl] + red[((16+row)*3+2)*16+dl]
                    + red[((32+row)*3+2)*16+dl] + red[((48+row)*3+2)*16+dl];
      float rr_ = sigm(xar + ar);
      float zz  = sigm(xaz + az);
      float nn  = tanhf(xan + rr_*an);
      float hv  = (1.f-zz)*nn + zz*shh[row*260+dg];
      g_hbuf[(t+1)&1][gr][dg] = hv;
      g_y0[(gr*32+t)*256+dg] = hv;
    }
    {
      int row = r2+8, gr = rowg*16 + row;
      float ar = br + red[((0+row)*3+0)*16+dl] + red[((16+row)*3+0)*16+dl]
                    + red[((32+row)*3+0)*16+dl] + red[((48+row)*3+0)*16+dl];
      float az = bz + red[((0+row)*3+1)*16+dl] + red[((16+row)*3+1)*16+dl]
                    + red[((32+row)*3+1)*16+dl] + red[((48+row)*3+1)*16+dl];
      float an = bn + red[((0+row)*3+2)*16+dl] + red[((16+row)*3+2)*16+dl]
                    + red[((32+row)*3+2)*16+dl] + red[((48+row)*3+2)*16+dl];
      float rr_ = sigm(xbr + ar);
      float zz  = sigm(xbz + az);
      float nn  = tanhf(xbn + rr_*an);
      float hv  = (1.f-zz)*nn + zz*shh[row*260+dg];
      g_hbuf[(t+1)&1][gr][dg] = hv;
      g_y0[(gr*32+t)*256+dg] = hv;
    }
    if (t < 31){
      __threadfence();
      __syncthreads();
      if (tid == 0) g_bf0[rowg][dsl] = (unsigned)(t+1);
    }
  }
}

// ---------------- GRU1 input gates: 2 cols/thread, prefetched weights -------
__global__ void __launch_bounds__(384) k_xg1(const float* __restrict__ bih1){
  __shared__ __align__(16) float sa[20][260];
  int tid = threadIdx.x;
  int m0 = blockIdx.x*20;
  for (int i=tid; i<20*64; i+=384){
    int r=i/64, k4=i%64;
    ((float4*)&sa[r][0])[k4] = *((const float4*)(g_y0 + (m0+r)*256) + k4);
  }
  __syncthreads();
  unsigned long long acc0[20], acc1[20];
  #pragma unroll
  for (int r=0;r<20;r++){ acc0[r]=0ull; acc1[r]=0ull; }
  const ulonglong2* wp = (const ulonglong2*)g_w1p4;
  int c0 = tid, c1 = tid + 384;
  ulonglong2 w0 = wp[c0], w1 = wp[c1];
  for (int k4=0;k4<64;k4++){
    ulonglong2 nw0, nw1;
    if (k4 < 63){
      nw0 = wp[(k4+1)*768 + c0];
      nw1 = wp[(k4+1)*768 + c1];
    }
    #pragma unroll
    for (int r=0;r<20;r++){
      ulonglong2 h = ((const ulonglong2*)&sa[r][0])[k4];
      fma2(acc0[r], w0.x, h.x); fma2(acc0[r], w0.y, h.y);
      fma2(acc1[r], w1.x, h.x); fma2(acc1[r], w1.y, h.y);
    }
    w0 = nw0; w1 = nw1;
  }
  float b0 = bih1[c0], b1 = bih1[c1];
  #pragma unroll
  for (int r=0;r<20;r++){
    g_xg1[(m0+r)*768 + c0] = b0 + s2(acc0[r]);
    g_xg1[(m0+r)*768 + c1] = b1 + s2(acc1[r]);
  }
}

// ---------------- GRU1 persistent scan, reg-weights, flag barrier -----------
// grid (16,8) x 128
__global__ void __launch_bounds__(128,1) k_gru1_scan(
    const float* __restrict__ whh, const float* __restrict__ bhh){
  __shared__ __align__(16) float shh[16*260];
  __shared__ float red[4*16*3*16];
  int tid = threadIdx.x;
  int dsl = blockIdx.x, rowg = blockIdx.y;
  int ks = tid >> 4, dl = tid & 15;
  int lane = tid & 31, w = tid >> 5;
  int dg = dsl*16 + dl;

  ulonglong2 warr[3][8];
  #pragma unroll
  for (int g=0; g<3; g++){
    const float* base = whh + (g*256 + dg)*256 + ks*32;
    #pragma unroll
    for (int jj=0; jj<8; jj++) warr[g][jj] = *(const ulonglong2*)(base + jj*4);
  }
  float br = bhh[dg], bz = bhh[256+dg], bn = bhh[512+dg];
  int r2 = ks;
  int grA = rowg*16 + r2, grB = grA + 8;
  int pA = grA>>6, bA = (grA>>5)&1, RA = grA&31; int pbA = pA*2+bA;
  int pB = grB>>6, bB = (grB>>5)&1, RB = grB&31; int pbB = pB*2+bB;
  __syncthreads();

  for (int t=0; t<20; t++){
    if (t > 0){
      if (tid < 16) while (g_bf1[rowg][tid] < (unsigned)t) { }
      __threadfence();
    }
    __syncthreads();
    if (t == 0){
      for (int i=tid; i<16*64; i+=128)
        ((float4*)(shh+(i>>6)*260))[i&63] = make_float4(0.f,0.f,0.f,0.f);
    } else {
      int par = t & 1;
      for (int i=tid; i<16*64; i+=128)
        ((float4*)(shh+(i>>6)*260))[i&63] =
            __ldcg(((const float4*)&g_hbuf[par][rowg*16+(i>>6)][0]) + (i&63));
    }
    __syncthreads();

    int xrowA = pbA*640 + RA*20 + t;
    int xrowB = pbB*640 + RB*20 + t;
    const float* xga = g_xg1 + xrowA*768;
    const float* xgb = g_xg1 + xrowB*768;
    float xar=xga[dg], xaz=xga[256+dg], xan=xga[512+dg];
    float xbr=xgb[dg], xbz=xgb[256+dg], xbn=xgb[512+dg];

    #pragma unroll
    for (int rc=0; rc<4; rc++){
      unsigned long long acc[4][3] = {};
      const float* hb = shh + (rc*4)*260 + ks*32;
      #pragma unroll
      for (int jj=0; jj<8; jj++){
        #pragma unroll
        for (int q=0; q<4; q++){
          ulonglong2 h2 = *(const ulonglong2*)(hb + q*260 + jj*4);
          fma2(acc[q][0], warr[0][jj].x, h2.x); fma2(acc[q][0], warr[0][jj].y, h2.y);
          fma2(acc[q][1], warr[1][jj].x, h2.x); fma2(acc[q][1], warr[1][jj].y, h2.y);
          fma2(acc[q][2], warr[2][jj].x, h2.x); fma2(acc[q][2], warr[2][jj].y, h2.y);
        }
      }
      #pragma unroll
      for (int q=0; q<4; q++){
        #pragma unroll
        for (int g=0; g<3; g++){
          float s = s2(acc[q][g]);
          s += __shfl_xor_sync(0xffffffffu, s, 16);
          if (lane < 16) red[((w*16 + rc*4+q)*3 + g)*16 + dl] = s;
        }
      }
    }
    __syncthreads();

    {
      int row = r2;
      float ar = br + red[((0+row)*3+0)*16+dl] + red[((16+row)*3+0)*16+dl]
                    + red[((32+row)*3+0)*16+dl] + red[((48+row)*3+0)*16+dl];
      float az = bz + red[((0+row)*3+1)*16+dl] + red[((16+row)*3+1)*16+dl]
                    + red[((32+row)*3+1)*16+dl] + red[((48+row)*3+1)*16+dl];
      float an = bn + red[((0+row)*3+2)*16+dl] + red[((16+row)*3+2)*16+dl]
                    + red[((32+row)*3+2)*16+dl] + red[((48+row)*3+2)*16+dl];
      float rr_ = sigm(xar + ar);
      float zz  = sigm(xaz + az);
      float nn  = tanhf(xan + rr_*an);
      float hv  = (1.f-zz)*nn + zz*shh[row*260+dg];
      g_hbuf[(t+1)&1][grA][dg] = hv;
      g_e[xrowA*256+dg] = hv;
    }
    {
      int row = r2+8;
      float ar = br + red[((0+row)*3+0)*16+dl] + red[((16+row)*3+0)*16+dl]
                    + red[((32+row)*3+0)*16+dl] + red[((48+row)*3+0)*16+dl];
      float az = bz + red[((0+row)*3+1)*16+dl] + red[((16+row)*3+1)*16+dl]
                    + red[((32+row)*3+1)*16+dl] + red[((48+row)*3+1)*16+dl];
      float an = bn + red[((0+row)*3+2)*16+dl] + red[((16+row)*3+2)*16+dl]
                    + red[((32+row)*3+2)*16+dl] + red[((48+row)*3+2)*16+dl];
      float rr_ = sigm(xbr + ar);
      float zz  = sigm(xbz + az);
      float nn  = tanhf(xbn + rr_*an);
      float hv  = (1.f-zz)*nn + zz*shh[row*260+dg];
      g_hbuf[(t+1)&1][grB][dg] = hv;
      g_e[xrowB*256+dg] = hv;
    }
    if (t < 19){
      __threadfence();
      __syncthreads();
      if (tid == 0) g_bf1[rowg][dsl] = (unsigned)(t+1);
    }
  }
}

// ---------------- q/k projection: prefetched packed GEMM --------------------
__global__ void __launch_bounds__(256) k_qk(
    const float* __restrict__ b1, const float* __restrict__ b2){
  __shared__ __align__(16) float sa[32][260];
  int tid = threadIdx.x;
  int which = blockIdx.y;
  int m0 = blockIdx.x*32;
  for (int i=tid; i<32*64; i+=256){
    int r=i>>6, k4=i&63;
    float4 v = *((const float4*)(g_e + (which*1280 + m0 + r)*256) + k4);
    v.x = v.x>0.f?v.x:0.f; v.y = v.y>0.f?v.y:0.f;
    v.z = v.z>0.f?v.z:0.f; v.w = v.w>0.f?v.w:0.f;
    ((float4*)&sa[r][0])[k4] = v;
  }
  __syncthreads();
  const ulonglong2* wp = (const ulonglong2*)(which ? g_j2p4 : g_j1p4);
  unsigned long long acc[32];
  #pragma unroll
  for (int r=0;r<32;r++) acc[r]=0ull;
  ulonglong2 w = wp[tid];
  for (int k4=0;k4<64;k4++){
    ulonglong2 nw;
    if (k4 < 63) nw = wp[(k4+1)*256 + tid];
    #pragma unroll
    for (int r=0;r<32;r++){
      ulonglong2 h = ((const ulonglong2*)&sa[r][0])[k4];
      fma2(acc[r], w.x, h.x);
      fma2(acc[r], w.y, h.y);
    }
    w = nw;
  }
  float bb = (which ? b2 : b1)[tid];
  float* out = which ? g_k : g_q;
  #pragma unroll
  for (int r=0;r<32;r++) out[(m0+r)*256+tid] = bb + s2(acc[r]);
}

// ---------------- inter (unnormalized sigmoid) + per-batch sum --------------
__global__ void k_inter(float* __restrict__ outp){
  __shared__ __align__(16) float qs[32][66], ks[32][66];
  __shared__ float red[256];
  int tid = threadIdx.x;
  int b = blockIdx.z, s0 = blockIdx.x*32, t0 = blockIdx.y*32;
  int si = tid>>3, tj = (tid&7)*4;
  unsigned long long a2[4] = {0ull,0ull,0ull,0ull};
  for (int kc=0; kc<4; kc++){
    for (int i=tid; i<2048; i+=256){
      int r = i>>6, c = i&63;
      qs[r][c] = g_q[(b*640+s0+r)*256 + kc*64 + c];
      ks[r][c] = g_k[(b*640+t0+r)*256 + kc*64 + c];
    }
    __syncthreads();
    #pragma unroll 8
    for (int kp=0;kp<32;kp++){
      unsigned long long qv = *(const unsigned long long*)&qs[si][2*kp];
      fma2(a2[0], qv, *(const unsigned long long*)&ks[tj+0][2*kp]);
      fma2(a2[1], qv, *(const unsigned long long*)&ks[tj+1][2*kp]);
      fma2(a2[2], qv, *(const unsigned long long*)&ks[tj+2][2*kp]);
      fma2(a2[3], qv, *(const unsigned long long*)&ks[tj+3][2*kp]);
    }
    __syncthreads();
  }
  float lsum = 0.f;
  #pragma unroll
  for (int u=0;u<4;u++){
    float v = sigm(s2(a2[u]));
    outp[b*409600 + (s0+si)*640 + (t0+tj+u)] = v;
    lsum += v;
  }
  red[tid]=lsum; __syncthreads();
  for (int off=128; off>0; off>>=1){ if (tid<off) red[tid]+=red[tid+off]; __syncthreads(); }
  if (tid==0) atomicAdd(&g_sum[b], red[0]);
}

// ---------------- pp accumulate (f32x2 poly) + normalize inter in place -----
__global__ void k_pp(float* __restrict__ outp){
  __shared__ __align__(16) float w[32][34];
  int tid = threadIdx.x, d = tid;
  int b = blockIdx.z, s0 = blockIdx.x*32, t0 = blockIdx.y*32;
  for (int i=tid; i<1024; i+=256){
    int si = i>>5, ti = i&31;
    w[si][ti] = outp[b*409600 + (s0+si)*640 + t0+ti];
  }
  float e2v[32]; float m2 = 0.f;
  #pragma unroll
  for (int ti=0; ti<32; ti++){
    e2v[ti] = g_e[((2+b)*640 + t0+ti)*256 + d];
    m2 = fmaxf(m2, fabsf(e2v[ti]));
  }
  unsigned long long e2p[16];
  #pragma unroll
  for (int u=0;u<16;u++) e2p[u] = pk2(e2v[2*u], e2v[2*u+1]);
  __syncthreads();
  const unsigned long long C5 = pk2(-0.0088632355f,-0.0088632355f);
  const unsigned long long C4 = pk2( 0.021869488f,  0.021869488f);
  const unsigned long long C3 = pk2(-0.053968254f, -0.053968254f);
  const unsigned long long C2 = pk2( 0.13333334f,   0.13333334f);
  const unsigned long long C1 = pk2(-0.33333334f,  -0.33333334f);
  unsigned long long acc2 = 0ull;
  float accS = 0.f;
  #pragma unroll 1
  for (int si=0; si<32; si++){
    float a = g_e[(b*640 + s0+si)*256 + d];
    if (fabsf(a)*m2 <= 0.6f){
      unsigned long long a2 = pk2(a, a);
      #pragma unroll
      for (int u=0;u<16;u++){
        unsigned long long x2 = mul2(a2, e2p[u]);
        unsigned long long u2 = mul2(x2, x2);
        unsigned long long p  = fma2r(u2, C5, C4);
        p = fma2r(u2, p, C3);
        p = fma2r(u2, p, C2);
        p = fma2r(u2, p, C1);
        unsigned long long tv = fma2r(mul2(x2,u2), p, x2);
        fma2(acc2, *(const unsigned long long*)&w[si][2*u], tv);
      }
    } else {
      for (int ti=0; ti<32; ti++){
        float x = a * g_e[((2+b)*640 + t0+ti)*256 + d];
        accS = fmaf(w[si][ti], tanhf(x), accS);
      }
    }
  }
  atomicAdd(&g_pp[b*256+d], accS + s2(acc2));
  float inv = 1.f/g_sum[b];
  for (int i=tid; i<1024; i+=256){
    int si = i>>5, ti = i&31;
    outp[b*409600 + (s0+si)*640 + t0+ti] = w[si][ti]*inv;
  }
}

// ---------------- head A: conv + leaky + maxpool; seed y1 with bias ---------
__global__ void k_headA(const float* __restrict__ cw_, const float* __restrict__ cb_,
                        const float* __restrict__ r1b){
  __shared__ float pp[256];
  __shared__ float cw[256];
  __shared__ float cb[64];
  int b = blockIdx.x, tid = threadIdx.x;
  float inv = 1.f/g_sum[b];
  pp[tid] = g_pp[b*256+tid]*inv;
  cw[tid] = cw_[tid];
  if (tid<64) cb[tid]=cb_[tid];
  __syncthreads();
  for (int idx=tid; idx<2048; idx+=256){
    int o = idx>>5, m = idx&31;
    float mx = -1e30f;
    for (int q=0;q<4;q++){
      int l = m*4+q;
      float s = cb[o];
      #pragma unroll
      for (int kk=0;kk<4;kk++){
        int pos = 2*l - 1 + kk;
        if (pos>=0 && pos<256) s = fmaf(pp[pos], cw[o*4+kk], s);
      }
      s = s>0.f ? s : 0.1f*s;
      mx = fmaxf(mx, s);
    }
    g_pool[b*2048+idx] = mx;
  }
  for (int j=tid; j<600; j+=256) g_y1[b*600+j] = r1b[j];
}

// ---------------- head B: r1 GEMV warp-per-row, k-split grid (4,2) ----------
__global__ void __launch_bounds__(256) k_headB(const float* __restrict__ r1w){
  __shared__ __align__(16) float spool[512];
  int kb = blockIdx.x, b = blockIdx.y;
  int tid = threadIdx.x, wid = tid>>5, lane = tid&31;
  for (int i=tid; i<512; i+=256) spool[i] = g_pool[b*2048 + kb*512 + i];
  __syncthreads();
  for (int j = wid; j < 600; j += 8){
    const float4* wr = (const float4*)(r1w + j*2048 + kb*512);
    float s = 0.f;
    #pragma unroll
    for (int it=0; it<4; it++){
      float4 wv = wr[it*32 + lane];
      float4 pv = *(const float4*)&spool[(it*32+lane)*4];
      s += wv.x*pv.x + wv.y*pv.y + wv.z*pv.z + wv.w*pv.w;
    }
    #pragma unroll
    for (int off=16; off; off>>=1) s += __shfl_xor_sync(0xffffffffu, s, off);
    if (lane==0) atomicAdd(&g_y1[b*600+j], s);
  }
}

// ---------------- head C: leaky -> r2 -> leaky -> r3 -> affn ----------------
__global__ void k_headC(const float* __restrict__ r2w, const float* __restrict__ r2b,
                        const float* __restrict__ r3w, const float* __restrict__ r3b,
                        float* __restrict__ outp){
  __shared__ __align__(16) float y1s[600];
  __shared__ float y2s[300];
  __shared__ float red[256];
  int b = blockIdx.x, tid = threadIdx.x;
  int wid = tid>>5, lane = tid&31;
  for (int j=tid; j<600; j+=256){
    float v = g_y1[b*600+j];
    y1s[j] = v>0.f ? v : 0.1f*v;
  }
  __syncthreads();
  for (int j = wid; j < 300; j += 8){
    const float* wr = r2w + j*600;
    float s = 0.f;
    for (int k = lane*4; k < 600; k += 128){
      float4 wv = *(const float4*)(wr + k);
      s += wv.x*y1s[k] + wv.y*y1s[k+1] + wv.z*y1s[k+2] + wv.w*y1s[k+3];
    }
    #pragma unroll
    for (int off=16; off; off>>=1) s += __shfl_xor_sync(0xffffffffu, s, off);
    if (lane==0){
      float v = s + r2b[j];
      y2s[j] = v>0.f ? v : 0.1f*v;
    }
  }
  __syncthreads();
  float part = 0.f;
  for (int k=tid; k<300; k+=256) part = fmaf(y2s[k], r3w[k], part);
  red[tid]=part; __syncthreads();
  for (int off=128; off>0; off>>=1){ if (tid<off) red[tid]+=red[tid+off]; __syncthreads(); }
  if (tid==0) outp[819200+b] = red[0] + r3b[0];
}

// ---------------- launch ----------------------------------------------------
extern "C" void kernel_launch(void* const* d_in, const int* in_sizes, int n_in,
                              void* d_out, int out_size){
  const int*   p1     = (const int*)  d_in[0];
  const int*   p2     = (const int*)  d_in[1];
  const float* emb    = (const float*)d_in[2];
  const float* g0_wih = (const float*)d_in[3];
  const float* g0_whh = (const float*)d_in[4];
  const float* g0_bih = (const float*)d_in[5];
  const float* g0_bhh = (const float*)d_in[6];
  const float* g1_wih = (const float*)d_in[7];
  const float* g1_whh = (const float*)d_in[8];
  const float* g1_bih = (const float*)d_in[9];
  const float* g1_bhh = (const float*)d_in[10];
  const float* ja1_w  = (const float*)d_in[11];
  const float* ja1_b  = (const float*)d_in[12];
  const float* ja2_w  = (const float*)d_in[13];
  const float* ja2_b  = (const float*)d_in[14];
  const float* conv_w = (const float*)d_in[15];
  const float* conv_b = (const float*)d_in[16];
  const float* r1w    = (const float*)d_in[17];
  const float* r1b    = (const float*)d_in[18];
  const float* r2w    = (const float*)d_in[19];
  const float* r2b    = (const float*)d_in[20];
  const float* r3w    = (const float*)d_in[21];
  const float* r3b    = (const float*)d_in[22];
  float* outp = (float*)d_out;

  k_nop<<<1,32>>>();
  k_pack<<<320,256>>>(g1_wih, ja1_w, ja2_w);
  k_tokxg<<<29,768>>>(emb, g0_wih, g0_bih);
  k_gru0_scan<<<dim3(16,5),128>>>(g0_whh, g0_bhh, p1, p2);
  k_xg1<<<128,384>>>(g1_bih);
  k_gru1_scan<<<dim3(16,8),128>>>(g1_whh, g1_bhh);
  k_qk<<<dim3(40,2),256>>>(ja1_b, ja2_b);
  dim3 gi(20,20,2);
  k_inter<<<gi,256>>>(outp);
  k_pp<<<gi,256>>>(outp);
  k_headA<<<2,256>>>(conv_w, conv_b, r1b);
  k_headB<<<dim3(4,2),256>>>(r1w);
  k_headC<<<2,256>>>(r2w, r2b, r3w, r3b, outp);
}

// round 16
// speedup vs baseline: 1.2070x; 1.0095x over previous
#include <cuda_runtime.h>
#include <math.h>

// Shapes: B=2, I=20, J=32, D=256, S=640, gates=768
__device__ float4 g_w1p4[49152];
__device__ float4 g_j1p4[16384];
__device__ float4 g_j2p4[16384];
__device__ float g_tokxg[29*768];
__device__ float g_hbuf[2][128][256];
__device__ float g_y0[2560*256];
__device__ float g_xg1[2560*768];
__device__ float g_e[4*640*256];
__device__ float g_q[1280*256];
__device__ float g_k[1280*256];
__device__ float g_sum[2];
__device__ float g_pp[512];
__device__ float g_pool[2*2048];
__device__ float g_y1[2*600];
__device__ volatile unsigned g_bf0[5][16];   // gru0 flags [rowg][dsl]
__device__ unsigned g_bcnt1[8];              // gru1 groupbar counters
__device__ volatile unsigned g_bflag1[8];

__device__ __forceinline__ float sigm(float x){ return 1.0f/(1.0f+expf(-x)); }

__device__ __forceinline__ unsigned long long pk2(float a, float b){
  unsigned long long r;
  asm("mov.b64 %0, {%1, %2};" : "=l"(r) : "f"(a), "f"(b));
  return r;
}
__device__ __forceinline__ float s2(unsigned long long v){
  float a, b;
  asm("mov.b64 {%0, %1}, %2;" : "=f"(a), "=f"(b) : "l"(v));
  return a + b;
}
__device__ __forceinline__ unsigned long long mul2(unsigned long long a, unsigned long long b){
  unsigned long long r;
  asm("mul.rn.f32x2 %0, %1, %2;" : "=l"(r) : "l"(a), "l"(b));
  return r;
}
__device__ __forceinline__ void fma2(unsigned long long &d, unsigned long long a, unsigned long long b){
  asm("fma.rn.f32x2 %0, %1, %2, %0;" : "+l"(d) : "l"(a), "l"(b));
}
__device__ __forceinline__ unsigned long long fma2r(unsigned long long a, unsigned long long b, unsigned long long c){
  unsigned long long r;
  asm("fma.rn.f32x2 %0, %1, %2, %3;" : "=l"(r) : "l"(a), "l"(b), "l"(c));
  return r;
}

__global__ void k_nop(){}

// ---------------- pack weights + zero accumulators/flags --------------------
__global__ void k_pack(const float* __restrict__ wih1, const float* __restrict__ ja1,
                       const float* __restrict__ ja2){
  int idx = blockIdx.x*256 + threadIdx.x;
  if (idx < 49152){
    int g = idx % 768, k4 = idx / 768;
    g_w1p4[idx] = *(const float4*)(wih1 + g*256 + k4*4);
  } else if (idx < 65536){
    int i = idx - 49152; int d = i % 256, k4 = i / 256;
    g_j1p4[i] = *(const float4*)(ja1 + d*256 + k4*4);
  } else {
    int i = idx - 65536; int d = i % 256, k4 = i / 256;
    g_j2p4[i] = *(const float4*)(ja2 + d*256 + k4*4);
  }
  if (idx < 512) g_pp[idx] = 0.f;
  if (idx < 2)   g_sum[idx] = 0.f;
  if (idx < 80)  ((volatile unsigned*)g_bf0)[idx] = 0u;
  if (idx < 8){ g_bcnt1[idx] = 0u; g_bflag1[idx] = 0u; }
}

// ---------------- token -> GRU0 input-gate table (29 x 768) -----------------
__global__ void k_tokxg(const float* __restrict__ emb, const float* __restrict__ wih0,
                        const float* __restrict__ bih0){
  __shared__ __align__(16) float se[256];
  int tok = blockIdx.x, g = threadIdx.x;
  if (g < 256) se[g] = emb[tok*256+g];
  __syncthreads();
  const ulonglong2* w2 = (const ulonglong2*)(wih0 + g*256);
  const ulonglong2* e2 = (const ulonglong2*)se;
  unsigned long long acc = 0ull;
  #pragma unroll 8
  for (int k=0;k<64;k++){
    ulonglong2 w = w2[k]; ulonglong2 e = e2[k];
    fma2(acc, w.x, e.x); fma2(acc, w.y, e.y);
  }
  g_tokxg[tok*768+g] = bih0[g] + s2(acc);
}

// ---------------- gru1 groupbar (atomic + tight spin, R12-proven) -----------
__device__ __forceinline__ void groupbar(unsigned* cnt, volatile unsigned* flag,
                                         unsigned gen, unsigned nblk){
  __threadfence();
  __syncthreads();
  if (threadIdx.x == 0){
    unsigned arr = atomicAdd(cnt, 1u) + 1u;
    if (arr == nblk*gen) *flag = gen;
    else while (*flag < gen) { }
    __threadfence();
  }
  __syncthreads();
}

// ---------------- GRU0 persistent scan, reg-weights, flag barrier -----------
// grid (16,5) x 128. thread: ks=tid>>4, dl=tid&15.
__global__ void __launch_bounds__(128,1) k_gru0_scan(
    const float* __restrict__ whh, const float* __restrict__ bhh,
    const int* __restrict__ p1, const int* __restrict__ p2){
  __shared__ __align__(16) float shh[16*260];
  __shared__ float red[4*16*3*16];   // [w][row][gate][dl]
  __shared__ int stok[16*32];
  int tid = threadIdx.x;
  int dsl = blockIdx.x, rowg = blockIdx.y;
  int ks = tid >> 4, dl = tid & 15;
  int lane = tid & 31, w = tid >> 5;
  int dg = dsl*16 + dl;

  ulonglong2 warr[3][8];
  #pragma unroll
  for (int g=0; g<3; g++){
    const float* base = whh + (g*256 + dg)*256 + ks*32;
    #pragma unroll
    for (int jj=0; jj<8; jj++) warr[g][jj] = *(const ulonglong2*)(base + jj*4);
  }
  for (int i = tid; i < 16*32; i += 128){
    int rr = i>>5, t = i&31;
    int gr = rowg*16 + rr;
    int p = gr/40, rem = gr - p*40, b = rem/20, ii = rem - b*20;
    stok[rr*32+t] = (p ? p2 : p1)[b*640 + ii*32 + t];
  }
  float br = bhh[dg], bz = bhh[256+dg], bn = bhh[512+dg];
  int r2 = ks;
  __syncthreads();

  for (int t=0; t<32; t++){
    if (t > 0){
      if (tid < 16) while (g_bf0[rowg][tid] < (unsigned)t) { }
      __threadfence();
    }
    __syncthreads();
    if (t == 0){
      for (int i=tid; i<16*64; i+=128)
        ((float4*)(shh+(i>>6)*260))[i&63] = make_float4(0.f,0.f,0.f,0.f);
    } else {
      int par = t & 1;
      for (int i=tid; i<16*64; i+=128)
        ((float4*)(shh+(i>>6)*260))[i&63] =
            __ldcg(((const float4*)&g_hbuf[par][rowg*16+(i>>6)][0]) + (i&63));
    }
    __syncthreads();

    const float* xga = g_tokxg + stok[r2*32+t]*768;
    const float* xgb = g_tokxg + stok[(r2+8)*32+t]*768;
    float xar=xga[dg], xaz=xga[256+dg], xan=xga[512+dg];
    float xbr=xgb[dg], xbz=xgb[256+dg], xbn=xgb[512+dg];

    #pragma unroll
    for (int rc=0; rc<4; rc++){
      unsigned long long acc[4][3] = {};
      const float* hb = shh + (rc*4)*260 + ks*32;
      #pragma unroll
      for (int jj=0; jj<8; jj++){
        #pragma unroll
        for (int q=0; q<4; q++){
          ulonglong2 h2 = *(const ulonglong2*)(hb + q*260 + jj*4);
          fma2(acc[q][0], warr[0][jj].x, h2.x); fma2(acc[q][0], warr[0][jj].y, h2.y);
          fma2(acc[q][1], warr[1][jj].x, h2.x); fma2(acc[q][1], warr[1][jj].y, h2.y);
          fma2(acc[q][2], warr[2][jj].x, h2.x); fma2(acc[q][2], warr[2][jj].y, h2.y);
        }
      }
      #pragma unroll
      for (int q=0; q<4; q++){
        #pragma unroll
        for (int g=0; g<3; g++){
          float s = s2(acc[q][g]);
          s += __shfl_xor_sync(0xffffffffu, s, 16);
          if (lane < 16) red[((w*16 + rc*4+q)*3 + g)*16 + dl] = s;
        }
      }
    }
    __syncthreads();

    {
      int row = r2, gr = rowg*16 + row;
      float ar = br + red[((0+row)*3+0)*16+dl] + red[((16+row)*3+0)*16+dl]
                    + red[((32+row)*3+0)*16+dl] + red[((48+row)*3+0)*16+dl];
      float az = bz + red[((0+row)*3+1)*16+dl] + red[((16+row)*3+1)*16+dl]
                    + red[((32+row)*3+1)*16+dl] + red[((48+row)*3+1)*16+dl];
      float an = bn + red[((0+row)*3+2)*16+dl] + red[((16+row)*3+2)*16+dl]
                    + red[((32+row)*3+2)*16+dl] + red[((48+row)*3+2)*16+dl];
      float rr_ = sigm(xar + ar);
      float zz  = sigm(xaz + az);
      float nn  = tanhf(xan + rr_*an);
      float hv  = (1.f-zz)*nn + zz*shh[row*260+dg];
      g_hbuf[(t+1)&1][gr][dg] = hv;
      g_y0[(gr*32+t)*256+dg] = hv;
    }
    {
      int row = r2+8, gr = rowg*16 + row;
      float ar = br + red[((0+row)*3+0)*16+dl] + red[((16+row)*3+0)*16+dl]
                    + red[((32+row)*3+0)*16+dl] + red[((48+row)*3+0)*16+dl];
      float az = bz + red[((0+row)*3+1)*16+dl] + red[((16+row)*3+1)*16+dl]
                    + red[((32+row)*3+1)*16+dl] + red[((48+row)*3+1)*16+dl];
      float an = bn + red[((0+row)*3+2)*16+dl] + red[((16+row)*3+2)*16+dl]
                    + red[((32+row)*3+2)*16+dl] + red[((48+row)*3+2)*16+dl];
      float rr_ = sigm(xbr + ar);
      float zz  = sigm(xbz + az);
      float nn  = tanhf(xbn + rr_*an);
      float hv  = (1.f-zz)*nn + zz*shh[row*260+dg];
      g_hbuf[(t+1)&1][gr][dg] = hv;
      g_y0[(gr*32+t)*256+dg] = hv;
    }
    if (t < 31){
      __threadfence();
      __syncthreads();
      if (tid == 0) g_bf0[rowg][dsl] = (unsigned)(t+1);
    }
  }
}

// ---------------- GRU1 input gates: 2 cols/thread, prefetched weights -------
__global__ void __launch_bounds__(384) k_xg1(const float* __restrict__ bih1){
  __shared__ __align__(16) float sa[20][260];
  int tid = threadIdx.x;
  int m0 = blockIdx.x*20;
  for (int i=tid; i<20*64; i+=384){
    int r=i/64, k4=i%64;
    ((float4*)&sa[r][0])[k4] = *((const float4*)(g_y0 + (m0+r)*256) + k4);
  }
  __syncthreads();
  unsigned long long acc0[20], acc1[20];
  #pragma unroll
  for (int r=0;r<20;r++){ acc0[r]=0ull; acc1[r]=0ull; }
  const ulonglong2* wp = (const ulonglong2*)g_w1p4;
  int c0 = tid, c1 = tid + 384;
  ulonglong2 w0 = wp[c0], w1 = wp[c1];
  for (int k4=0;k4<64;k4++){
    ulonglong2 nw0, nw1;
    if (k4 < 63){
      nw0 = wp[(k4+1)*768 + c0];
      nw1 = wp[(k4+1)*768 + c1];
    }
    #pragma unroll
    for (int r=0;r<20;r++){
      ulonglong2 h = ((const ulonglong2*)&sa[r][0])[k4];
      fma2(acc0[r], w0.x, h.x); fma2(acc0[r], w0.y, h.y);
      fma2(acc1[r], w1.x, h.x); fma2(acc1[r], w1.y, h.y);
    }
    w0 = nw0; w1 = nw1;
  }
  float b0 = bih1[c0], b1 = bih1[c1];
  #pragma unroll
  for (int r=0;r<20;r++){
    g_xg1[(m0+r)*768 + c0] = b0 + s2(acc0[r]);
    g_xg1[(m0+r)*768 + c1] = b1 + s2(acc1[r]);
  }
}

// ---------------- GRU1 persistent scan, reg-weights, groupbar ---------------
// grid (16,8) x 128
__global__ void __launch_bounds__(128,1) k_gru1_scan(
    const float* __restrict__ whh, const float* __restrict__ bhh){
  __shared__ __align__(16) float shh[16*260];
  __shared__ float red[4*16*3*16];
  int tid = threadIdx.x;
  int dsl = blockIdx.x, rowg = blockIdx.y;
  int ks = tid >> 4, dl = tid & 15;
  int lane = tid & 31, w = tid >> 5;
  int dg = dsl*16 + dl;

  ulonglong2 warr[3][8];
  #pragma unroll
  for (int g=0; g<3; g++){
    const float* base = whh + (g*256 + dg)*256 + ks*32;
    #pragma unroll
    for (int jj=0; jj<8; jj++) warr[g][jj] = *(const ulonglong2*)(base + jj*4);
  }
  float br = bhh[dg], bz = bhh[256+dg], bn = bhh[512+dg];
  int r2 = ks;
  int grA = rowg*16 + r2, grB = grA + 8;
  int pA = grA>>6, bA = (grA>>5)&1, RA = grA&31; int pbA = pA*2+bA;
  int pB = grB>>6, bB = (grB>>5)&1, RB = grB&31; int pbB = pB*2+bB;
  __syncthreads();

  for (int t=0; t<20; t++){
    if (t == 0){
      for (int i=tid; i<16*64; i+=128)
        ((float4*)(shh+(i>>6)*260))[i&63] = make_float4(0.f,0.f,0.f,0.f);
    } else {
      int par = t & 1;
      for (int i=tid; i<16*64; i+=128)
        ((float4*)(shh+(i>>6)*260))[i&63] =
            __ldcg(((const float4*)&g_hbuf[par][rowg*16+(i>>6)][0]) + (i&63));
    }
    __syncthreads();

    int xrowA = pbA*640 + RA*20 + t;
    int xrowB = pbB*640 + RB*20 + t;
    const float* xga = g_xg1 + xrowA*768;
    const float* xgb = g_xg1 + xrowB*768;
    float xar=xga[dg], xaz=xga[256+dg], xan=xga[512+dg];
    float xbr=xgb[dg], xbz=xgb[256+dg], xbn=xgb[512+dg];

    #pragma unroll
    for (int rc=0; rc<4; rc++){
      unsigned long long acc[4][3] = {};
      const float* hb = shh + (rc*4)*260 + ks*32;
      #pragma unroll
      for (int jj=0; jj<8; jj++){
        #pragma unroll
        for (int q=0; q<4; q++){
          ulonglong2 h2 = *(const ulonglong2*)(hb + q*260 + jj*4);
          fma2(acc[q][0], warr[0][jj].x, h2.x); fma2(acc[q][0], warr[0][jj].y, h2.y);
          fma2(acc[q][1], warr[1][jj].x, h2.x); fma2(acc[q][1], warr[1][jj].y, h2.y);
          fma2(acc[q][2], warr[2][jj].x, h2.x); fma2(acc[q][2], warr[2][jj].y, h2.y);
        }
      }
      #pragma unroll
      for (int q=0; q<4; q++){
        #pragma unroll
        for (int g=0; g<3; g++){
          float s = s2(acc[q][g]);
          s += __shfl_xor_sync(0xffffffffu, s, 16);
          if (lane < 16) red[((w*16 + rc*4+q)*3 + g)*16 + dl] = s;
        }
      }
    }
    __syncthreads();

    {
      int row = r2;
      float ar = br + red[((0+row)*3+0)*16+dl] + red[((16+row)*3+0)*16+dl]
                    + red[((32+row)*3+0)*16+dl] + red[((48+row)*3+0)*16+dl];
      float az = bz + red[((0+row)*3+1)*16+dl] + red[((16+row)*3+1)*16+dl]
                    + red[((32+row)*3+1)*16+dl] + red[((48+row)*3+1)*16+dl];
      float an = bn + red[((0+row)*3+2)*16+dl] + red[((16+row)*3+2)*16+dl]
                    + red[((32+row)*3+2)*16+dl] + red[((48+row)*3+2)*16+dl];
      float rr_ = sigm(xar + ar);
      float zz  = sigm(xaz + az);
      float nn  = tanhf(xan + rr_*an);
      float hv  = (1.f-zz)*nn + zz*shh[row*260+dg];
      g_hbuf[(t+1)&1][grA][dg] = hv;
      g_e[xrowA*256+dg] = hv;
    }
    {
      int row = r2+8;
      float ar = br + red[((0+row)*3+0)*16+dl] + red[((16+row)*3+0)*16+dl]
                    + red[((32+row)*3+0)*16+dl] + red[((48+row)*3+0)*16+dl];
      float az = bz + red[((0+row)*3+1)*16+dl] + red[((16+row)*3+1)*16+dl]
                    + red[((32+row)*3+1)*16+dl] + red[((48+row)*3+1)*16+dl];
      float an = bn + red[((0+row)*3+2)*16+dl] + red[((16+row)*3+2)*16+dl]
                    + red[((32+row)*3+2)*16+dl] + red[((48+row)*3+2)*16+dl];
      float rr_ = sigm(xbr + ar);
      float zz  = sigm(xbz + az);
      float nn  = tanhf(xbn + rr_*an);
      float hv  = (1.f-zz)*nn + zz*shh[row*260+dg];
      g_hbuf[(t+1)&1][grB][dg] = hv;
      g_e[xrowB*256+dg] = hv;
    }
    if (t < 19) groupbar(&g_bcnt1[rowg], &g_bflag1[rowg], t+1, 16);
  }
}

// ---------------- q/k projection: prefetched packed GEMM --------------------
__global__ void __launch_bounds__(256) k_qk(
    const float* __restrict__ b1, const float* __restrict__ b2){
  __shared__ __align__(16) float sa[32][260];
  int tid = threadIdx.x;
  int which = blockIdx.y;
  int m0 = blockIdx.x*32;
  for (int i=tid; i<32*64; i+=256){
    int r=i>>6, k4=i&63;
    float4 v = *((const float4*)(g_e + (which*1280 + m0 + r)*256) + k4);
    v.x = v.x>0.f?v.x:0.f; v.y = v.y>0.f?v.y:0.f;
    v.z = v.z>0.f?v.z:0.f; v.w = v.w>0.f?v.w:0.f;
    ((float4*)&sa[r][0])[k4] = v;
  }
  __syncthreads();
  const ulonglong2* wp = (const ulonglong2*)(which ? g_j2p4 : g_j1p4);
  unsigned long long acc[32];
  #pragma unroll
  for (int r=0;r<32;r++) acc[r]=0ull;
  ulonglong2 w = wp[tid];
  for (int k4=0;k4<64;k4++){
    ulonglong2 nw;
    if (k4 < 63) nw = wp[(k4+1)*256 + tid];
    #pragma unroll
    for (int r=0;r<32;r++){
      ulonglong2 h = ((const ulonglong2*)&sa[r][0])[k4];
      fma2(acc[r], w.x, h.x);
      fma2(acc[r], w.y, h.y);
    }
    w = nw;
  }
  float bb = (which ? b2 : b1)[tid];
  float* out = which ? g_k : g_q;
  #pragma unroll
  for (int r=0;r<32;r++) out[(m0+r)*256+tid] = bb + s2(acc[r]);
}

// ---------------- inter (unnormalized sigmoid) + per-batch sum --------------
__global__ void k_inter(float* __restrict__ outp){
  __shared__ __align__(16) float qs[32][66], ks[32][66];
  __shared__ float red[256];
  int tid = threadIdx.x;
  int b = blockIdx.z, s0 = blockIdx.x*32, t0 = blockIdx.y*32;
  int si = tid>>3, tj = (tid&7)*4;
  unsigned long long a2[4] = {0ull,0ull,0ull,0ull};
  for (int kc=0; kc<4; kc++){
    for (int i=tid; i<2048; i+=256){
      int r = i>>6, c = i&63;
      qs[r][c] = g_q[(b*640+s0+r)*256 + kc*64 + c];
      ks[r][c] = g_k[(b*640+t0+r)*256 + kc*64 + c];
    }
    __syncthreads();
    #pragma unroll 8
    for (int kp=0;kp<32;kp++){
      unsigned long long qv = *(const unsigned long long*)&qs[si][2*kp];
      fma2(a2[0], qv, *(const unsigned long long*)&ks[tj+0][2*kp]);
      fma2(a2[1], qv, *(const unsigned long long*)&ks[tj+1][2*kp]);
      fma2(a2[2], qv, *(const unsigned long long*)&ks[tj+2][2*kp]);
      fma2(a2[3], qv, *(const unsigned long long*)&ks[tj+3][2*kp]);
    }
    __syncthreads();
  }
  float lsum = 0.f;
  #pragma unroll
  for (int u=0;u<4;u++){
    float v = sigm(s2(a2[u]));
    outp[b*409600 + (s0+si)*640 + (t0+tj+u)] = v;
    lsum += v;
  }
  red[tid]=lsum; __syncthreads();
  for (int off=128; off>0; off>>=1){ if (tid<off) red[tid]+=red[tid+off]; __syncthreads(); }
  if (tid==0) atomicAdd(&g_sum[b], red[0]);
}

// ---------------- pp accumulate (f32x2 poly) + normalize inter in place -----
__global__ void k_pp(float* __restrict__ outp){
  __shared__ __align__(16) float w[32][34];
  int tid = threadIdx.x, d = tid;
  int b = blockIdx.z, s0 = blockIdx.x*32, t0 = blockIdx.y*32;
  for (int i=tid; i<1024; i+=256){
    int si = i>>5, ti = i&31;
    w[si][ti] = outp[b*409600 + (s0+si)*640 + t0+ti];
  }
  float e2v[32]; float m2 = 0.f;
  #pragma unroll
  for (int ti=0; ti<32; ti++){
    e2v[ti] = g_e[((2+b)*640 + t0+ti)*256 + d];
    m2 = fmaxf(m2, fabsf(e2v[ti]));
  }
  unsigned long long e2p[16];
  #pragma unroll
  for (int u=0;u<16;u++) e2p[u] = pk2(e2v[2*u], e2v[2*u+1]);
  __syncthreads();
  const unsigned long long C5 = pk2(-0.0088632355f,-0.0088632355f);
  const unsigned long long C4 = pk2( 0.021869488f,  0.021869488f);
  const unsigned long long C3 = pk2(-0.053968254f, -0.053968254f);
  const unsigned long long C2 = pk2( 0.13333334f,   0.13333334f);
  const unsigned long long C1 = pk2(-0.33333334f,  -0.33333334f);
  unsigned long long acc2 = 0ull;
  float accS = 0.f;
  #pragma unroll 1
  for (int si=0; si<32; si++){
    float a = g_e[(b*640 + s0+si)*256 + d];
    if (fabsf(a)*m2 <= 0.6f){
      unsigned long long a2 = pk2(a, a);
      #pragma unroll
      for (int u=0;u<16;u++){
        unsigned long long x2 = mul2(a2, e2p[u]);
        unsigned long long u2 = mul2(x2, x2);
        unsigned long long p  = fma2r(u2, C5, C4);
        p = fma2r(u2, p, C3);
        p = fma2r(u2, p, C2);
        p = fma2r(u2, p, C1);
        unsigned long long tv = fma2r(mul2(x2,u2), p, x2);
        fma2(acc2, *(const unsigned long long*)&w[si][2*u], tv);
      }
    } else {
      for (int ti=0; ti<32; ti++){
        float x = a * g_e[((2+b)*640 + t0+ti)*256 + d];
        accS = fmaf(w[si][ti], tanhf(x), accS);
      }
    }
  }
  atomicAdd(&g_pp[b*256+d], accS + s2(acc2));
  float inv = 1.f/g_sum[b];
  for (int i=tid; i<1024; i+=256){
    int si = i>>5, ti = i&31;
    outp[b*409600 + (s0+si)*640 + t0+ti] = w[si][ti]*inv;
  }
}

// ---------------- head A: conv + leaky + maxpool; seed y1 with bias ---------
__global__ void k_headA(const float* __restrict__ cw_, const float* __restrict__ cb_,
                        const float* __restrict__ r1b){
  __shared__ float pp[256];
  __shared__ float cw[256];
  __shared__ float cb[64];
  int b = blockIdx.x, tid = threadIdx.x;
  float inv = 1.f/g_sum[b];
  pp[tid] = g_pp[b*256+tid]*inv;
  cw[tid] = cw_[tid];
  if (tid<64) cb[tid]=cb_[tid];
  __syncthreads();
  for (int idx=tid; idx<2048; idx+=256){
    int o = idx>>5, m = idx&31;
    float mx = -1e30f;
    for (int q=0;q<4;q++){
      int l = m*4+q;
      float s = cb[o];
      #pragma unroll
      for (int kk=0;kk<4;kk++){
        int pos = 2*l - 1 + kk;
        if (pos>=0 && pos<256) s = fmaf(pp[pos], cw[o*4+kk], s);
      }
      s = s>0.f ? s : 0.1f*s;
      mx = fmaxf(mx, s);
    }
    g_pool[b*2048+idx] = mx;
  }
  for (int j=tid; j<600; j+=256) g_y1[b*600+j] = r1b[j];
}

// ---------------- head B: r1 GEMV warp-per-row, k-split grid (4,2) ----------
__global__ void __launch_bounds__(256) k_headB(const float* __restrict__ r1w){
  __shared__ __align__(16) float spool[512];
  int kb = blockIdx.x, b = blockIdx.y;
  int tid = threadIdx.x, wid = tid>>5, lane = tid&31;
  for (int i=tid; i<512; i+=256) spool[i] = g_pool[b*2048 + kb*512 + i];
  __syncthreads();
  for (int j = wid; j < 600; j += 8){
    const float4* wr = (const float4*)(r1w + j*2048 + kb*512);
    float s = 0.f;
    #pragma unroll
    for (int it=0; it<4; it++){
      float4 wv = wr[it*32 + lane];
      float4 pv = *(const float4*)&spool[(it*32+lane)*4];
      s += wv.x*pv.x + wv.y*pv.y + wv.z*pv.z + wv.w*pv.w;
    }
    #pragma unroll
    for (int off=16; off; off>>=1) s += __shfl_xor_sync(0xffffffffu, s, off);
    if (lane==0) atomicAdd(&g_y1[b*600+j], s);
  }
}

// ---------------- head C: leaky -> r2 -> leaky -> r3 -> affn ----------------
__global__ void k_headC(const float* __restrict__ r2w, const float* __restrict__ r2b,
                        const float* __restrict__ r3w, const float* __restrict__ r3b,
                        float* __restrict__ outp){
  __shared__ __align__(16) float y1s[600];
  __shared__ float y2s[300];
  __shared__ float red[256];
  int b = blockIdx.x, tid = threadIdx.x;
  int wid = tid>>5, lane = tid&31;
  for (int j=tid; j<600; j+=256){
    float v = g_y1[b*600+j];
    y1s[j] = v>0.f ? v : 0.1f*v;
  }
  __syncthreads();
  for (int j = wid; j < 300; j += 8){
    const float* wr = r2w + j*600;
    float s = 0.f;
    for (int k = lane*4; k < 600; k += 128){
      float4 wv = *(const float4*)(wr + k);
      s += wv.x*y1s[k] + wv.y*y1s[k+1] + wv.z*y1s[k+2] + wv.w*y1s[k+3];
    }
    #pragma unroll
    for (int off=16; off; off>>=1) s += __shfl_xor_sync(0xffffffffu, s, off);
    if (lane==0){
      float v = s + r2b[j];
      y2s[j] = v>0.f ? v : 0.1f*v;
    }
  }
  __syncthreads();
  float part = 0.f;
  for (int k=tid; k<300; k+=256) part = fmaf(y2s[k], r3w[k], part);
  red[tid]=part; __syncthreads();
  for (int off=128; off>0; off>>=1){ if (tid<off) red[tid]+=red[tid+off]; __syncthreads(); }
  if (tid==0) outp[819200+b] = red[0] + r3b[0];
}

// ---------------- launch ----------------------------------------------------
extern "C" void kernel_launch(void* const* d_in, const int* in_sizes, int n_in,
                              void* d_out, int out_size){
  const int*   p1     = (const int*)  d_in[0];
  const int*   p2     = (const int*)  d_in[1];
  const float* emb    = (const float*)d_in[2];
  const float* g0_wih = (const float*)d_in[3];
  const float* g0_whh = (const float*)d_in[4];
  const float* g0_bih = (const float*)d_in[5];
  const float* g0_bhh = (const float*)d_in[6];
  const float* g1_wih = (const float*)d_in[7];
  const float* g1_whh = (const float*)d_in[8];
  const float* g1_bih = (const float*)d_in[9];
  const float* g1_bhh = (const float*)d_in[10];
  const float* ja1_w  = (const float*)d_in[11];
  const float* ja1_b  = (const float*)d_in[12];
  const float* ja2_w  = (const float*)d_in[13];
  const float* ja2_b  = (const float*)d_in[14];
  const float* conv_w = (const float*)d_in[15];
  const float* conv_b = (const float*)d_in[16];
  const float* r1w    = (const float*)d_in[17];
  const float* r1b    = (const float*)d_in[18];
  const float* r2w    = (const float*)d_in[19];
  const float* r2b    = (const float*)d_in[20];
  const float* r3w    = (const float*)d_in[21];
  const float* r3b    = (const float*)d_in[22];
  float* outp = (float*)d_out;

  k_nop<<<1,32>>>();
  k_pack<<<320,256>>>(g1_wih, ja1_w, ja2_w);
  k_tokxg<<<29,768>>>(emb, g0_wih, g0_bih);
  k_gru0_scan<<<dim3(16,5),128>>>(g0_whh, g0_bhh, p1, p2);
  k_xg1<<<128,384>>>(g1_bih);
  k_gru1_scan<<<dim3(16,8),128>>>(g1_whh, g1_bhh);
  k_qk<<<dim3(40,2),256>>>(ja1_b, ja2_b);
  dim3 gi(20,20,2);
  k_inter<<<gi,256>>>(outp);
  k_pp<<<gi,256>>>(outp);
  k_headA<<<2,256>>>(conv_w, conv_b, r1b);
  k_headB<<<dim3(4,2),256>>>(r1w);
  k_headC<<<2,256>>>(r2w, r2b, r3w, r3b, outp);
}

// round 17
// speedup vs baseline: 1.2503x; 1.0359x over previous
#include <cuda_runtime.h>
#include <math.h>

// Shapes: B=2, I=20, J=32, D=256, S=640, gates=768
__device__ float4 g_w1p4[49152];
__device__ float4 g_j1p4[16384];
__device__ float4 g_j2p4[16384];
__device__ float g_tokxg[29*768];
__device__ float g_hbuf[2][128][256];
__device__ float g_y0[2560*256];
__device__ float g_xg1[2560*768];
__device__ float g_e[4*640*256];
__device__ float g_q[1280*256];
__device__ float g_k[1280*256];
__device__ float g_sum[2];
__device__ float g_pp[512];
__device__ float g_pool[2*2048];
__device__ float g_y1[2*600];
__device__ unsigned g_bcnt0[5];
__device__ volatile unsigned g_bflag0[5];
__device__ unsigned g_bcnt1[8];
__device__ volatile unsigned g_bflag1[8];

__device__ __forceinline__ float sigm(float x){ return 1.0f/(1.0f+expf(-x)); }

__device__ __forceinline__ unsigned long long pk2(float a, float b){
  unsigned long long r;
  asm("mov.b64 %0, {%1, %2};" : "=l"(r) : "f"(a), "f"(b));
  return r;
}
__device__ __forceinline__ float s2(unsigned long long v){
  float a, b;
  asm("mov.b64 {%0, %1}, %2;" : "=f"(a), "=f"(b) : "l"(v));
  return a + b;
}
__device__ __forceinline__ unsigned long long mul2(unsigned long long a, unsigned long long b){
  unsigned long long r;
  asm("mul.rn.f32x2 %0, %1, %2;" : "=l"(r) : "l"(a), "l"(b));
  return r;
}
__device__ __forceinline__ void fma2(unsigned long long &d, unsigned long long a, unsigned long long b){
  asm("fma.rn.f32x2 %0, %1, %2, %0;" : "+l"(d) : "l"(a), "l"(b));
}
__device__ __forceinline__ unsigned long long fma2r(unsigned long long a, unsigned long long b, unsigned long long c){
  unsigned long long r;
  asm("fma.rn.f32x2 %0, %1, %2, %3;" : "=l"(r) : "l"(a), "l"(b), "l"(c));
  return r;
}

// ---------------- pack weights + zero accumulators (320 x 256) --------------
__global__ void k_pack(const float* __restrict__ wih1, const float* __restrict__ ja1,
                       const float* __restrict__ ja2){
  int idx = blockIdx.x*256 + threadIdx.x;
  if (idx < 49152){
    int g = idx % 768, k4 = idx / 768;
    g_w1p4[idx] = *(const float4*)(wih1 + g*256 + k4*4);
  } else if (idx < 65536){
    int i = idx - 49152; int d = i % 256, k4 = i / 256;
    g_j1p4[i] = *(const float4*)(ja1 + d*256 + k4*4);
  } else {
    int i = idx - 65536; int d = i % 256, k4 = i / 256;
    g_j2p4[i] = *(const float4*)(ja2 + d*256 + k4*4);
  }
  if (idx < 512) g_pp[idx] = 0.f;
  if (idx < 2)   g_sum[idx] = 0.f;
  if (idx < 5){ g_bcnt0[idx] = 0u; g_bflag0[idx] = 0u; }
  if (idx < 8){ g_bcnt1[idx] = 0u; g_bflag1[idx] = 0u; }
}

// ---------------- token -> GRU0 input-gate table (29 x 768) -----------------
__global__ void k_tokxg(const float* __restrict__ emb, const float* __restrict__ wih0,
                        const float* __restrict__ bih0){
  __shared__ __align__(16) float se[256];
  int tok = blockIdx.x, g = threadIdx.x;
  if (g < 256) se[g] = emb[tok*256+g];
  __syncthreads();
  const ulonglong2* w2 = (const ulonglong2*)(wih0 + g*256);
  const ulonglong2* e2 = (const ulonglong2*)se;
  unsigned long long acc = 0ull;
  #pragma unroll 8
  for (int k=0;k<64;k++){
    ulonglong2 w = w2[k]; ulonglong2 e = e2[k];
    fma2(acc, w.x, e.x); fma2(acc, w.y, e.y);
  }
  g_tokxg[tok*768+g] = bih0[g] + s2(acc);
}

// ---------------- software sub-grid barrier (tight spin) --------------------
__device__ __forceinline__ void groupbar(unsigned* cnt, volatile unsigned* flag,
                                         unsigned gen, unsigned nblk){
  __threadfence();
  __syncthreads();
  if (threadIdx.x == 0){
    unsigned arr = atomicAdd(cnt, 1u) + 1u;
    if (arr == nblk*gen) *flag = gen;
    else while (*flag < gen) { }
    __threadfence();
  }
  __syncthreads();
}

// ---------------- GRU0 persistent scan, reg-weights + ksplit ----------------
// grid (16,5) x 128. thread: ks=tid>>4 (k-range 32), dl=tid&15.
__global__ void __launch_bounds__(128,1) k_gru0_scan(
    const float* __restrict__ whh, const float* __restrict__ bhh,
    const int* __restrict__ p1, const int* __restrict__ p2){
  __shared__ __align__(16) float shh[16*260];
  __shared__ float red[4*16*3*16];   // [w][row][gate][dl]
  __shared__ int stok[16*32];
  int tid = threadIdx.x;
  int dsl = blockIdx.x, rowg = blockIdx.y;
  int ks = tid >> 4, dl = tid & 15;
  int lane = tid & 31, w = tid >> 5;
  int dg = dsl*16 + dl;

  ulonglong2 warr[3][8];
  #pragma unroll
  for (int g=0; g<3; g++){
    const float* base = whh + (g*256 + dg)*256 + ks*32;
    #pragma unroll
    for (int jj=0; jj<8; jj++) warr[g][jj] = *(const ulonglong2*)(base + jj*4);
  }
  for (int i = tid; i < 16*32; i += 128){
    int rr = i>>5, t = i&31;
    int gr = rowg*16 + rr;
    int p = gr/40, rem = gr - p*40, b = rem/20, ii = rem - b*20;
    stok[rr*32+t] = (p ? p2 : p1)[b*640 + ii*32 + t];
  }
  float br = bhh[dg], bz = bhh[256+dg], bn = bhh[512+dg];
  int r2 = ks;
  __syncthreads();

  for (int t=0; t<32; t++){
    if (t == 0){
      for (int i=tid; i<16*64; i+=128)
        ((float4*)(shh+(i>>6)*260))[i&63] = make_float4(0.f,0.f,0.f,0.f);
    } else {
      int par = t & 1;
      for (int i=tid; i<16*64; i+=128)
        ((float4*)(shh+(i>>6)*260))[i&63] =
            __ldcg(((const float4*)&g_hbuf[par][rowg*16+(i>>6)][0]) + (i&63));
    }
    __syncthreads();

    const float* xga = g_tokxg + stok[r2*32+t]*768;
    const float* xgb = g_tokxg + stok[(r2+8)*32+t]*768;
    float xar=xga[dg], xaz=xga[256+dg], xan=xga[512+dg];
    float xbr=xgb[dg], xbz=xgb[256+dg], xbn=xgb[512+dg];

    #pragma unroll
    for (int rc=0; rc<4; rc++){
      unsigned long long acc[4][3] = {};
      const float* hb = shh + (rc*4)*260 + ks*32;
      #pragma unroll
      for (int jj=0; jj<8; jj++){
        #pragma unroll
        for (int q=0; q<4; q++){
          ulonglong2 h2 = *(const ulonglong2*)(hb + q*260 + jj*4);
          fma2(acc[q][0], warr[0][jj].x, h2.x); fma2(acc[q][0], warr[0][jj].y, h2.y);
          fma2(acc[q][1], warr[1][jj].x, h2.x); fma2(acc[q][1], warr[1][jj].y, h2.y);
          fma2(acc[q][2], warr[2][jj].x, h2.x); fma2(acc[q][2], warr[2][jj].y, h2.y);
        }
      }
      #pragma unroll
      for (int q=0; q<4; q++){
        #pragma unroll
        for (int g=0; g<3; g++){
          float s = s2(acc[q][g]);
          s += __shfl_xor_sync(0xffffffffu, s, 16);
          if (lane < 16) red[((w*16 + rc*4+q)*3 + g)*16 + dl] = s;
        }
      }
    }
    __syncthreads();

    {
      int row = r2, gr = rowg*16 + row;
      float ar = br + red[((0+row)*3+0)*16+dl] + red[((16+row)*3+0)*16+dl]
                    + red[((32+row)*3+0)*16+dl] + red[((48+row)*3+0)*16+dl];
      float az = bz + red[((0+row)*3+1)*16+dl] + red[((16+row)*3+1)*16+dl]
                    + red[((32+row)*3+1)*16+dl] + red[((48+row)*3+1)*16+dl];
      float an = bn + red[((0+row)*3+2)*16+dl] + red[((16+row)*3+2)*16+dl]
                    + red[((32+row)*3+2)*16+dl] + red[((48+row)*3+2)*16+dl];
      float rr_ = sigm(xar + ar);
      float zz  = sigm(xaz + az);
      float nn  = tanhf(xan + rr_*an);
      float hv  = (1.f-zz)*nn + zz*shh[row*260+dg];
      g_hbuf[(t+1)&1][gr][dg] = hv;
      g_y0[(gr*32+t)*256+dg] = hv;
    }
    {
      int row = r2+8, gr = rowg*16 + row;
      float ar = br + red[((0+row)*3+0)*16+dl] + red[((16+row)*3+0)*16+dl]
                    + red[((32+row)*3+0)*16+dl] + red[((48+row)*3+0)*16+dl];
      float az = bz + red[((0+row)*3+1)*16+dl] + red[((16+row)*3+1)*16+dl]
                    + red[((32+row)*3+1)*16+dl] + red[((48+row)*3+1)*16+dl];
      float an = bn + red[((0+row)*3+2)*16+dl] + red[((16+row)*3+2)*16+dl]
                    + red[((32+row)*3+2)*16+dl] + red[((48+row)*3+2)*16+dl];
      float rr_ = sigm(xbr + ar);
      float zz  = sigm(xbz + az);
      float nn  = tanhf(xbn + rr_*an);
      float hv  = (1.f-zz)*nn + zz*shh[row*260+dg];
      g_hbuf[(t+1)&1][gr][dg] = hv;
      g_y0[(gr*32+t)*256+dg] = hv;
    }
    if (t < 31) groupbar(&g_bcnt0[rowg], &g_bflag0[rowg], t+1, 16);
  }
}

// ---------------- GRU1 input gates: 10 rows/block x 256 blocks --------------
__global__ void __launch_bounds__(384) k_xg1(const float* __restrict__ bih1){
  __shared__ __align__(16) float sa[10][260];
  int tid = threadIdx.x;
  int m0 = blockIdx.x*10;
  for (int i=tid; i<10*64; i+=384){
    int r=i/64, k4=i%64;
    ((float4*)&sa[r][0])[k4] = *((const float4*)(g_y0 + (m0+r)*256) + k4);
  }
  __syncthreads();
  unsigned long long acc0[10], acc1[10];
  #pragma unroll
  for (int r=0;r<10;r++){ acc0[r]=0ull; acc1[r]=0ull; }
  const ulonglong2* wp = (const ulonglong2*)g_w1p4;
  int c0 = tid, c1 = tid + 384;
  ulonglong2 w0 = wp[c0], w1 = wp[c1];
  for (int k4=0;k4<64;k4++){
    ulonglong2 nw0, nw1;
    if (k4 < 63){
      nw0 = wp[(k4+1)*768 + c0];
      nw1 = wp[(k4+1)*768 + c1];
    }
    #pragma unroll
    for (int r=0;r<10;r++){
      ulonglong2 h = ((const ulonglong2*)&sa[r][0])[k4];
      fma2(acc0[r], w0.x, h.x); fma2(acc0[r], w0.y, h.y);
      fma2(acc1[r], w1.x, h.x); fma2(acc1[r], w1.y, h.y);
    }
    w0 = nw0; w1 = nw1;
  }
  float b0 = bih1[c0], b1 = bih1[c1];
  #pragma unroll
  for (int r=0;r<10;r++){
    g_xg1[(m0+r)*768 + c0] = b0 + s2(acc0[r]);
    g_xg1[(m0+r)*768 + c1] = b1 + s2(acc1[r]);
  }
}

// ---------------- GRU1 persistent scan, reg-weights + ksplit ----------------
// grid (16,8) x 128
__global__ void __launch_bounds__(128,1) k_gru1_scan(
    const float* __restrict__ whh, const float* __restrict__ bhh){
  __shared__ __align__(16) float shh[16*260];
  __shared__ float red[4*16*3*16];
  int tid = threadIdx.x;
  int dsl = blockIdx.x, rowg = blockIdx.y;
  int ks = tid >> 4, dl = tid & 15;
  int lane = tid & 31, w = tid >> 5;
  int dg = dsl*16 + dl;

  ulonglong2 warr[3][8];
  #pragma unroll
  for (int g=0; g<3; g++){
    const float* base = whh + (g*256 + dg)*256 + ks*32;
    #pragma unroll
    for (int jj=0; jj<8; jj++) warr[g][jj] = *(const ulonglong2*)(base + jj*4);
  }
  float br = bhh[dg], bz = bhh[256+dg], bn = bhh[512+dg];
  int r2 = ks;
  int grA = rowg*16 + r2, grB = grA + 8;
  int pA = grA>>6, bA = (grA>>5)&1, RA = grA&31; int pbA = pA*2+bA;
  int pB = grB>>6, bB = (grB>>5)&1, RB = grB&31; int pbB = pB*2+bB;
  __syncthreads();

  for (int t=0; t<20; t++){
    if (t == 0){
      for (int i=tid; i<16*64; i+=128)
        ((float4*)(shh+(i>>6)*260))[i&63] = make_float4(0.f,0.f,0.f,0.f);
    } else {
      int par = t & 1;
      for (int i=tid; i<16*64; i+=128)
        ((float4*)(shh+(i>>6)*260))[i&63] =
            __ldcg(((const float4*)&g_hbuf[par][rowg*16+(i>>6)][0]) + (i&63));
    }
    __syncthreads();

    int xrowA = pbA*640 + RA*20 + t;
    int xrowB = pbB*640 + RB*20 + t;
    const float* xga = g_xg1 + xrowA*768;
    const float* xgb = g_xg1 + xrowB*768;
    float xar=xga[dg], xaz=xga[256+dg], xan=xga[512+dg];
    float xbr=xgb[dg], xbz=xgb[256+dg], xbn=xgb[512+dg];

    #pragma unroll
    for (int rc=0; rc<4; rc++){
      unsigned long long acc[4][3] = {};
      const float* hb = shh + (rc*4)*260 + ks*32;
      #pragma unroll
      for (int jj=0; jj<8; jj++){
        #pragma unroll
        for (int q=0; q<4; q++){
          ulonglong2 h2 = *(const ulonglong2*)(hb + q*260 + jj*4);
          fma2(acc[q][0], warr[0][jj].x, h2.x); fma2(acc[q][0], warr[0][jj].y, h2.y);
          fma2(acc[q][1], warr[1][jj].x, h2.x); fma2(acc[q][1], warr[1][jj].y, h2.y);
          fma2(acc[q][2], warr[2][jj].x, h2.x); fma2(acc[q][2], warr[2][jj].y, h2.y);
        }
      }
      #pragma unroll
      for (int q=0; q<4; q++){
        #pragma unroll
        for (int g=0; g<3; g++){
          float s = s2(acc[q][g]);
          s += __shfl_xor_sync(0xffffffffu, s, 16);
          if (lane < 16) red[((w*16 + rc*4+q)*3 + g)*16 + dl] = s;
        }
      }
    }
    __syncthreads();

    {
      int row = r2;
      float ar = br + red[((0+row)*3+0)*16+dl] + red[((16+row)*3+0)*16+dl]
                    + red[((32+row)*3+0)*16+dl] + red[((48+row)*3+0)*16+dl];
      float az = bz + red[((0+row)*3+1)*16+dl] + red[((16+row)*3+1)*16+dl]
                    + red[((32+row)*3+1)*16+dl] + red[((48+row)*3+1)*16+dl];
      float an = bn + red[((0+row)*3+2)*16+dl] + red[((16+row)*3+2)*16+dl]
                    + red[((32+row)*3+2)*16+dl] + red[((48+row)*3+2)*16+dl];
      float rr_ = sigm(xar + ar);
      float zz  = sigm(xaz + az);
      float nn  = tanhf(xan + rr_*an);
      float hv  = (1.f-zz)*nn + zz*shh[row*260+dg];
      g_hbuf[(t+1)&1][grA][dg] = hv;
      g_e[xrowA*256+dg] = hv;
    }
    {
      int row = r2+8;
      float ar = br + red[((0+row)*3+0)*16+dl] + red[((16+row)*3+0)*16+dl]
                    + red[((32+row)*3+0)*16+dl] + red[((48+row)*3+0)*16+dl];
      float az = bz + red[((0+row)*3+1)*16+dl] + red[((16+row)*3+1)*16+dl]
                    + red[((32+row)*3+1)*16+dl] + red[((48+row)*3+1)*16+dl];
      float an = bn + red[((0+row)*3+2)*16+dl] + red[((16+row)*3+2)*16+dl]
                    + red[((32+row)*3+2)*16+dl] + red[((48+row)*3+2)*16+dl];
      float rr_ = sigm(xbr + ar);
      float zz  = sigm(xbz + az);
      float nn  = tanhf(xbn + rr_*an);
      float hv  = (1.f-zz)*nn + zz*shh[row*260+dg];
      g_hbuf[(t+1)&1][grB][dg] = hv;
      g_e[xrowB*256+dg] = hv;
    }
    if (t < 19) groupbar(&g_bcnt1[rowg], &g_bflag1[rowg], t+1, 16);
  }
}

// ---------------- q/k projection: prefetched packed GEMM --------------------
__global__ void __launch_bounds__(256) k_qk(
    const float* __restrict__ b1, const float* __restrict__ b2){
  __shared__ __align__(16) float sa[32][260];
  int tid = threadIdx.x;
  int which = blockIdx.y;
  int m0 = blockIdx.x*32;
  for (int i=tid; i<32*64; i+=256){
    int r=i>>6, k4=i&63;
    float4 v = *((const float4*)(g_e + (which*1280 + m0 + r)*256) + k4);
    v.x = v.x>0.f?v.x:0.f; v.y = v.y>0.f?v.y:0.f;
    v.z = v.z>0.f?v.z:0.f; v.w = v.w>0.f?v.w:0.f;
    ((float4*)&sa[r][0])[k4] = v;
  }
  __syncthreads();
  const ulonglong2* wp = (const ulonglong2*)(which ? g_j2p4 : g_j1p4);
  unsigned long long acc[32];
  #pragma unroll
  for (int r=0;r<32;r++) acc[r]=0ull;
  ulonglong2 w = wp[tid];
  for (int k4=0;k4<64;k4++){
    ulonglong2 nw;
    if (k4 < 63) nw = wp[(k4+1)*256 + tid];
    #pragma unroll
    for (int r=0;r<32;r++){
      ulonglong2 h = ((const ulonglong2*)&sa[r][0])[k4];
      fma2(acc[r], w.x, h.x);
      fma2(acc[r], w.y, h.y);
    }
    w = nw;
  }
  float bb = (which ? b2 : b1)[tid];
  float* out = which ? g_k : g_q;
  #pragma unroll
  for (int r=0;r<32;r++) out[(m0+r)*256+tid] = bb + s2(acc[r]);
}

// ---------------- inter (unnormalized sigmoid) + per-batch sum --------------
__global__ void k_inter(float* __restrict__ outp){
  __shared__ __align__(16) float qs[32][66], ks[32][66];
  __shared__ float red[256];
  int tid = threadIdx.x;
  int b = blockIdx.z, s0 = blockIdx.x*32, t0 = blockIdx.y*32;
  int si = tid>>3, tj = (tid&7)*4;
  unsigned long long a2[4] = {0ull,0ull,0ull,0ull};
  for (int kc=0; kc<4; kc++){
    for (int i=tid; i<2048; i+=256){
      int r = i>>6, c = i&63;
      qs[r][c] = g_q[(b*640+s0+r)*256 + kc*64 + c];
      ks[r][c] = g_k[(b*640+t0+r)*256 + kc*64 + c];
    }
    __syncthreads();
    #pragma unroll 8
    for (int kp=0;kp<32;kp++){
      unsigned long long qv = *(const unsigned long long*)&qs[si][2*kp];
      fma2(a2[0], qv, *(const unsigned long long*)&ks[tj+0][2*kp]);
      fma2(a2[1], qv, *(const unsigned long long*)&ks[tj+1][2*kp]);
      fma2(a2[2], qv, *(const unsigned long long*)&ks[tj+2][2*kp]);
      fma2(a2[3], qv, *(const unsigned long long*)&ks[tj+3][2*kp]);
    }
    __syncthreads();
  }
  float lsum = 0.f;
  #pragma unroll
  for (int u=0;u<4;u++){
    float v = sigm(s2(a2[u]));
    outp[b*409600 + (s0+si)*640 + (t0+tj+u)] = v;
    lsum += v;
  }
  red[tid]=lsum; __syncthreads();
  for (int off=128; off>0; off>>=1){ if (tid<off) red[tid]+=red[tid+off]; __syncthreads(); }
  if (tid==0) atomicAdd(&g_sum[b], red[0]);
}

// ---------------- pp accumulate (f32x2 poly) + normalize inter in place -----
__global__ void k_pp(float* __restrict__ outp){
  __shared__ __align__(16) float w[32][34];
  int tid = threadIdx.x, d = tid;
  int b = blockIdx.z, s0 = blockIdx.x*32, t0 = blockIdx.y*32;
  for (int i=tid; i<1024; i+=256){
    int si = i>>5, ti = i&31;
    w[si][ti] = outp[b*409600 + (s0+si)*640 + t0+ti];
  }
  float e2v[32]; float m2 = 0.f;
  #pragma unroll
  for (int ti=0; ti<32; ti++){
    e2v[ti] = g_e[((2+b)*640 + t0+ti)*256 + d];
    m2 = fmaxf(m2, fabsf(e2v[ti]));
  }
  unsigned long long e2p[16];
  #pragma unroll
  for (int u=0;u<16;u++) e2p[u] = pk2(e2v[2*u], e2v[2*u+1]);
  __syncthreads();
  const unsigned long long C5 = pk2(-0.0088632355f,-0.0088632355f);
  const unsigned long long C4 = pk2( 0.021869488f,  0.021869488f);
  const unsigned long long C3 = pk2(-0.053968254f, -0.053968254f);
  const unsigned long long C2 = pk2( 0.13333334f,   0.13333334f);
  const unsigned long long C1 = pk2(-0.33333334f,  -0.33333334f);
  unsigned long long acc2 = 0ull;
  float accS = 0.f;
  #pragma unroll 1
  for (int si=0; si<32; si++){
    float a = g_e[(b*640 + s0+si)*256 + d];
    if (fabsf(a)*m2 <= 0.6f){
      unsigned long long a2 = pk2(a, a);
      #pragma unroll
      for (int u=0;u<16;u++){
        unsigned long long x2 = mul2(a2, e2p[u]);
        unsigned long long u2 = mul2(x2, x2);
        unsigned long long p  = fma2r(u2, C5, C4);
        p = fma2r(u2, p, C3);
        p = fma2r(u2, p, C2);
        p = fma2r(u2, p, C1);
        unsigned long long tv = fma2r(mul2(x2,u2), p, x2);
        fma2(acc2, *(const unsigned long long*)&w[si][2*u], tv);
      }
    } else {
      for (int ti=0; ti<32; ti++){
        float x = a * g_e[((2+b)*640 + t0+ti)*256 + d];
        accS = fmaf(w[si][ti], tanhf(x), accS);
      }
    }
  }
  atomicAdd(&g_pp[b*256+d], accS + s2(acc2));
  float inv = 1.f/g_sum[b];
  for (int i=tid; i<1024; i+=256){
    int si = i>>5, ti = i&31;
    outp[b*409600 + (s0+si)*640 + t0+ti] = w[si][ti]*inv;
  }
}

// ---------------- head A: conv + leaky + maxpool; seed y1 with bias ---------
__global__ void k_headA(const float* __restrict__ cw_, const float* __restrict__ cb_,
                        const float* __restrict__ r1b){
  __shared__ float pp[256];
  __shared__ float cw[256];
  __shared__ float cb[64];
  int b = blockIdx.x, tid = threadIdx.x;
  float inv = 1.f/g_sum[b];
  pp[tid] = g_pp[b*256+tid]*inv;
  cw[tid] = cw_[tid];
  if (tid<64) cb[tid]=cb_[tid];
  __syncthreads();
  for (int idx=tid; idx<2048; idx+=256){
    int o = idx>>5, m = idx&31;
    float mx = -1e30f;
    for (int q=0;q<4;q++){
      int l = m*4+q;
      float s = cb[o];
      #pragma unroll
      for (int kk=0;kk<4;kk++){
        int pos = 2*l - 1 + kk;
        if (pos>=0 && pos<256) s = fmaf(pp[pos], cw[o*4+kk], s);
      }
      s = s>0.f ? s : 0.1f*s;
      mx = fmaxf(mx, s);
    }
    g_pool[b*2048+idx] = mx;
  }
  for (int j=tid; j<600; j+=256) g_y1[b*600+j] = r1b[j];
}

// ---------------- head B: r1 GEMV warp-per-row, k-split grid (4,2) ----------
__global__ void __launch_bounds__(256) k_headB(const float* __restrict__ r1w){
  __shared__ __align__(16) float spool[512];
  int kb = blockIdx.x, b = blockIdx.y;
  int tid = threadIdx.x, wid = tid>>5, lane = tid&31;
  for (int i=tid; i<512; i+=256) spool[i] = g_pool[b*2048 + kb*512 + i];
  __syncthreads();
  for (int j = wid; j < 600; j += 8){
    const float4* wr = (const float4*)(r1w + j*2048 + kb*512);
    float s = 0.f;
    #pragma unroll
    for (int it=0; it<4; it++){
      float4 wv = wr[it*32 + lane];
      float4 pv = *(const float4*)&spool[(it*32+lane)*4];
      s += wv.x*pv.x + wv.y*pv.y + wv.z*pv.z + wv.w*pv.w;
    }
    #pragma unroll
    for (int off=16; off; off>>=1) s += __shfl_xor_sync(0xffffffffu, s, off);
    if (lane==0) atomicAdd(&g_y1[b*600+j], s);
  }
}

// ---------------- head C: leaky -> r2 -> leaky -> r3 -> affn ----------------
__global__ void k_headC(const float* __restrict__ r2w, const float* __restrict__ r2b,
                        const float* __restrict__ r3w, const float* __restrict__ r3b,
                        float* __restrict__ outp){
  __shared__ __align__(16) float y1s[600];
  __shared__ float y2s[300];
  __shared__ float red[256];
  int b = blockIdx.x, tid = threadIdx.x;
  int wid = tid>>5, lane = tid&31;
  for (int j=tid; j<600; j+=256){
    float v = g_y1[b*600+j];
    y1s[j] = v>0.f ? v : 0.1f*v;
  }
  __syncthreads();
  for (int j = wid; j < 300; j += 8){
    const float* wr = r2w + j*600;
    float s = 0.f;
    for (int k = lane*4; k < 600; k += 128){
      float4 wv = *(const float4*)(wr + k);
      s += wv.x*y1s[k] + wv.y*y1s[k+1] + wv.z*y1s[k+2] + wv.w*y1s[k+3];
    }
    #pragma unroll
    for (int off=16; off; off>>=1) s += __shfl_xor_sync(0xffffffffu, s, off);
    if (lane==0){
      float v = s + r2b[j];
      y2s[j] = v>0.f ? v : 0.1f*v;
    }
  }
  __syncthreads();
  float part = 0.f;
  for (int k=tid; k<300; k+=256) part = fmaf(y2s[k], r3w[k], part);
  red[tid]=part; __syncthreads();
  for (int off=128; off>0; off>>=1){ if (tid<off) red[tid]+=red[tid+off]; __syncthreads(); }
  if (tid==0) outp[819200+b] = red[0] + r3b[0];
}

// ---------------- launch ----------------------------------------------------
extern "C" void kernel_launch(void* const* d_in, const int* in_sizes, int n_in,
                              void* d_out, int out_size){
  const int*   p1     = (const int*)  d_in[0];
  const int*   p2     = (const int*)  d_in[1];
  const float* emb    = (const float*)d_in[2];
  const float* g0_wih = (const float*)d_in[3];
  const float* g0_whh = (const float*)d_in[4];
  const float* g0_bih = (const float*)d_in[5];
  const float* g0_bhh = (const float*)d_in[6];
  const float* g1_wih = (const float*)d_in[7];
  const float* g1_whh = (const float*)d_in[8];
  const float* g1_bih = (const float*)d_in[9];
  const float* g1_bhh = (const float*)d_in[10];
  const float* ja1_w  = (const float*)d_in[11];
  const float* ja1_b  = (const float*)d_in[12];
  const float* ja2_w  = (const float*)d_in[13];
  const float* ja2_b  = (const float*)d_in[14];
  const float* conv_w = (const float*)d_in[15];
  const float* conv_b = (const float*)d_in[16];
  const float* r1w    = (const float*)d_in[17];
  const float* r1b    = (const float*)d_in[18];
  const float* r2w    = (const float*)d_in[19];
  const float* r2b    = (const float*)d_in[20];
  const float* r3w    = (const float*)d_in[21];
  const float* r3b    = (const float*)d_in[22];
  float* outp = (float*)d_out;

  k_pack<<<320,256>>>(g1_wih, ja1_w, ja2_w);
  k_tokxg<<<29,768>>>(emb, g0_wih, g0_bih);
  k_gru0_scan<<<dim3(16,5),128>>>(g0_whh, g0_bhh, p1, p2);
  k_xg1<<<256,384>>>(g1_bih);
  k_gru1_scan<<<dim3(16,8),128>>>(g1_whh, g1_bhh);
  k_qk<<<dim3(40,2),256>>>(ja1_b, ja2_b);
  dim3 gi(20,20,2);
  k_inter<<<gi,256>>>(outp);
  k_pp<<<gi,256>>>(outp);
  k_headA<<<2,256>>>(conv_w, conv_b, r1b);
  k_headB<<<dim3(4,2),256>>>(r1w);
  k_headC<<<2,256>>>(r2w, r2b, r3w, r3b, outp);
}